// round 11
// baseline (speedup 1.0000x reference)
#include <cuda_runtime.h>
#include <cuda_fp16.h>
#include <cstdint>
#include <math.h>

#define TOKENS  2048
#define HIDDEN  2048
#define INTER   1408
#define EXPERTS 16
#define MAXPAIRS (TOKENS*2)

// ---------------- scratch ----------------
__device__ int   g_cnt[EXPERTS];
__device__ int   g_off[EXPERTS + 1];
__device__ int   g_tok[EXPERTS * TOKENS];
__device__ int   g_te[MAXPAIRS];
__device__ int   g_tslot[MAXPAIRS];
__device__ float g_tw[MAXPAIRS];
__device__ float g_logits[TOKENS * EXPERTS];
__device__ float g_y[(size_t)MAXPAIRS * HIDDEN];

// fp16 operands (single-term)
__device__ __half c_Xh[(size_t)TOKENS * HIDDEN];
__device__ __half c_W0h[(size_t)EXPERTS * HIDDEN * INTER];
__device__ __half c_W1h[(size_t)EXPERTS * HIDDEN * INTER];
__device__ __half c_Wdh[(size_t)EXPERTS * INTER * HIDDEN];
__device__ __half g_hh[(size_t)(MAXPAIRS + 128) * INTER];

// ---------------- helpers ----------------
__device__ __forceinline__ float sigmoidf_fast(float x) { return 1.0f / (1.0f + __expf(-x)); }

__device__ __forceinline__ uint32_t smem_u32(const void* p) {
    uint32_t a;
    asm("{ .reg .u64 t; cvta.to.shared.u64 t, %1; cvt.u32.u64 %0, t; }" : "=r"(a) : "l"(p));
    return a;
}
__device__ __forceinline__ uint32_t cvt2h(float x, float y) {
    __half2 h = __floats2half2_rn(x, y);
    return *(uint32_t*)&h;
}
// m16n8k16 fp16 MMA, fp32 accum
__device__ __forceinline__ void mma16(float* d, const uint32_t* a, const uint32_t* b) {
    asm volatile("mma.sync.aligned.m16n8k16.row.col.f32.f16.f16.f32 "
        "{%0,%1,%2,%3}, {%4,%5,%6,%7}, {%8,%9}, {%0,%1,%2,%3};"
        : "+f"(d[0]), "+f"(d[1]), "+f"(d[2]), "+f"(d[3])
        : "r"(a[0]), "r"(a[1]), "r"(a[2]), "r"(a[3]), "r"(b[0]), "r"(b[1]));
}
#define LDSM4(r0,r1,r2,r3,addr) \
    asm volatile("ldmatrix.sync.aligned.m8n8.x4.shared.b16 {%0,%1,%2,%3}, [%4];" \
        : "=r"(r0), "=r"(r1), "=r"(r2), "=r"(r3) : "r"(addr))
#define LDSM4T(r0,r1,r2,r3,addr) \
    asm volatile("ldmatrix.sync.aligned.m8n8.x4.trans.shared.b16 {%0,%1,%2,%3}, [%4];" \
        : "=r"(r0), "=r"(r1), "=r"(r2), "=r"(r3) : "r"(addr))
#define CP16(dst, src, sz) \
    asm volatile("cp.async.cg.shared.global [%0], [%1], 16, %2;" \
        :: "r"(dst), "l"(src), "r"(sz) : "memory")
#define CP_COMMIT() asm volatile("cp.async.commit_group;" ::: "memory")
#define CP_WAIT1()  asm volatile("cp.async.wait_group 1;" ::: "memory")

// ---------------- conversion: fp32 -> fp16 ----------------
__global__ void cvt_kernel(const float* __restrict__ src,
                           __half* __restrict__ dst, int n8) {
    int i = blockIdx.x * blockDim.x + threadIdx.x;
    if (i >= n8) return;
    const float4* s = (const float4*)src + 2 * (size_t)i;
    float4 v0 = s[0], v1 = s[1];
    *(uint4*)(dst + 8 * (size_t)i) = make_uint4(
        cvt2h(v0.x, v0.y), cvt2h(v0.z, v0.w), cvt2h(v1.x, v1.y), cvt2h(v1.z, v1.w));
}

// ---------------- routing (proven) ----------------
__global__ void zero_cnt_kernel() { if (threadIdx.x < EXPERTS) g_cnt[threadIdx.x] = 0; }

__global__ void router_logits_kernel(const float* __restrict__ X, const float* __restrict__ Wg) {
    int idx = blockIdx.x * blockDim.x + threadIdx.x;
    int t = idx >> 4, e = idx & 15;
    const float* xr = X + (size_t)t * HIDDEN;
    float s0 = 0.f, s1 = 0.f, s2 = 0.f, s3 = 0.f;
    #pragma unroll 4
    for (int k = 0; k < HIDDEN; k += 4) {
        s0 = fmaf(xr[k+0], Wg[(k+0)*EXPERTS + e], s0);
        s1 = fmaf(xr[k+1], Wg[(k+1)*EXPERTS + e], s1);
        s2 = fmaf(xr[k+2], Wg[(k+2)*EXPERTS + e], s2);
        s3 = fmaf(xr[k+3], Wg[(k+3)*EXPERTS + e], s3);
    }
    g_logits[idx] = (s0 + s1) + (s2 + s3);
}

__global__ void router_topk_kernel() {
    int t = blockIdx.x * blockDim.x + threadIdx.x;
    if (t >= TOKENS) return;
    float l[EXPERTS];
    #pragma unroll
    for (int e = 0; e < EXPERTS; e++) l[e] = g_logits[t * EXPERTS + e];
    int e1 = 0; float v1 = l[0];
    #pragma unroll
    for (int e = 1; e < EXPERTS; e++) if (l[e] > v1) { v1 = l[e]; e1 = e; }
    int e2 = -1; float v2 = -3.4e38f;
    #pragma unroll
    for (int e = 0; e < EXPERTS; e++) { if (e == e1) continue; if (l[e] > v2) { v2 = l[e]; e2 = e; } }
    float w1 = sigmoidf_fast(v1), w2 = sigmoidf_fast(v2);
    float inv = 1.0f / (w1 + w2); w1 *= inv; w2 *= inv;
    int s1 = atomicAdd(&g_cnt[e1], 1);
    int s2 = atomicAdd(&g_cnt[e2], 1);
    g_tok[e1 * TOKENS + s1] = t;
    g_tok[e2 * TOKENS + s2] = t;
    g_te[2*t+0] = e1; g_tslot[2*t+0] = s1; g_tw[2*t+0] = w1;
    g_te[2*t+1] = e2; g_tslot[2*t+1] = s2; g_tw[2*t+1] = w2;
}

__global__ void offsets_kernel() {
    if (threadIdx.x == 0 && blockIdx.x == 0) {
        int a = 0;
        for (int e = 0; e < EXPERTS; e++) { g_off[e] = a; a += g_cnt[e]; }
        g_off[EXPERTS] = a;
    }
}

// ---------------- fp16 single-term mma.sync grouped GEMM, cp.async 3-stage ----------------
// FUSED=1: A = gathered Xh rows; B0=W0h(gate), B1=W1h(up); epi h=silu(g)*u -> g_hh (fp16)
// FUSED=0: A = g_hh rows;        B0=Wdh;                   epi raw -> g_y (fp32)
// ebase: first expert of this launch (expert id = ebase + blockIdx.z)
template <int FUSED>
__global__ __launch_bounds__(256, 1)
void moe_gemm_fp16(const __half* __restrict__ Agh,
                   const __half* __restrict__ B0h_g,
                   const __half* __restrict__ B1h_g,
                   int ebase) {
    constexpr int Kdim = FUSED ? HIDDEN : INTER;
    constexpr int Ndim = FUSED ? INTER : HIDDEN;
    constexpr int KT   = Kdim / 32;
    constexpr int SA   = 40;   // halves
    constexpr int SB   = 136;  // halves
    constexpr int B0H  = 128 * SA;          // 5120
    constexpr int B1H  = B0H + 32 * SB;
    constexpr int STAGE_H = B0H + (FUSED ? 2 : 1) * 32 * SB;
    constexpr int STAGE_B = STAGE_H * 2;

    const int e  = ebase + blockIdx.z;
    const int ne = g_cnt[e];
    const int m0 = blockIdx.x * 128;
    if (m0 >= ne) return;
    const int n0  = blockIdx.y * 128;
    const int off = g_off[e];

    extern __shared__ __align__(16) uint16_t smh[];
    const uint32_t sbase = smem_u32(smh);

    const int tid  = threadIdx.x;
    const int lane = tid & 31;
    const int wid  = tid >> 5;
    const int wm   = wid & 1;
    const int wn   = wid >> 1;
    const int lg   = lane >> 2;
    const int lt   = lane & 3;
    const int q    = lane >> 3;
    const int rr   = lane & 7;

    const uint32_t a_loff = (uint32_t)(((wm * 64 + (q & 1) * 8 + rr) * SA + (q >> 1) * 8) * 2);
    const uint32_t b_loff = (uint32_t)((rr * SB + wn * 32 + q * 8) * 2);

    // A: thread covers row (tid>>1), halves [(tid&1)*16, +16)
    const int ar  = tid >> 1;
    const int ach = (tid & 1) * 16;
    const __half* pAh;
    uint32_t aSz;
    {
        int r = m0 + ar;
        if (FUSED) {
            if (r < ne) {
                pAh = Agh + (size_t)g_tok[e * TOKENS + r] * Kdim + ach; aSz = 16;
            } else { pAh = Agh; aSz = 0; }
        } else {
            pAh = Agh + (size_t)(off + r) * Kdim + ach; aSz = 16;
        }
    }
    const uint32_t dA = (uint32_t)((ar * SA + ach) * 2);
    // B: thread covers k-row (tid>>3), halves [(tid&7)*16, +16)
    const int br  = tid >> 3;
    const int bch = (tid & 7) * 16;
    const size_t bstart = (size_t)e * Kdim * Ndim + (size_t)br * Ndim + n0 + bch;
    const __half* pB0h = B0h_g + bstart;
    const __half* pB1h = FUSED ? (B1h_g + bstart) : nullptr;
    const uint32_t dB = (uint32_t)((br * SB + bch) * 2);

    auto issue = [&](int kt, int buf) {
        const uint32_t st = sbase + (uint32_t)buf * STAGE_B;
        const size_t ak = (size_t)kt * 32;
        const size_t bk = (size_t)kt * 32 * Ndim;
        CP16(st + dA,                 pAh + ak,      aSz);
        CP16(st + dA + 16,            pAh + ak + 8,  aSz);
        CP16(st + dB + B0H * 2,       pB0h + bk,     16u);
        CP16(st + dB + B0H * 2 + 16,  pB0h + bk + 8, 16u);
        if (FUSED) {
            CP16(st + dB + B1H * 2,       pB1h + bk,     16u);
            CP16(st + dB + B1H * 2 + 16,  pB1h + bk + 8, 16u);
        }
    };

    float accG[4][4][4];
    float accU[FUSED ? 4 : 1][4][4];
    #pragma unroll
    for (int i = 0; i < 4; i++)
        #pragma unroll
        for (int j = 0; j < 4; j++)
            #pragma unroll
            for (int p = 0; p < 4; p++) { accG[i][j][p] = 0.f; if (FUSED) accU[i][j][p] = 0.f; }

    issue(0, 0); CP_COMMIT();
    if (KT > 1) issue(1, 1);
    CP_COMMIT();
    CP_WAIT1();
    __syncthreads();

    for (int kt = 0; kt < KT; kt++) {
        if (kt + 2 < KT) issue(kt + 2, (kt + 2) % 3);
        CP_COMMIT();

        const uint32_t st = sbase + (uint32_t)(kt % 3) * STAGE_B;
        #pragma unroll
        for (int ks = 0; ks < 2; ks++) {
            const uint32_t bks = (uint32_t)(ks * 16 * SB * 2);
            uint32_t bGh[4][2];
            uint32_t bUh[FUSED ? 4 : 1][2];
            {
                uint32_t t0, t1, t2, t3;
                uint32_t ba = st + (uint32_t)(B0H * 2) + b_loff + bks;
                LDSM4T(t0, t1, t2, t3, ba);
                bGh[0][0]=t0; bGh[1][0]=t1; bGh[2][0]=t2; bGh[3][0]=t3;
                LDSM4T(t0, t1, t2, t3, ba + 8 * SB * 2);
                bGh[0][1]=t0; bGh[1][1]=t1; bGh[2][1]=t2; bGh[3][1]=t3;
                if (FUSED) {
                    ba = st + (uint32_t)(B1H * 2) + b_loff + bks;
                    LDSM4T(t0, t1, t2, t3, ba);
                    bUh[0][0]=t0; bUh[1][0]=t1; bUh[2][0]=t2; bUh[3][0]=t3;
                    LDSM4T(t0, t1, t2, t3, ba + 8 * SB * 2);
                    bUh[0][1]=t0; bUh[1][1]=t1; bUh[2][1]=t2; bUh[3][1]=t3;
                }
            }
            #pragma unroll
            for (int mf = 0; mf < 4; mf++) {
                uint32_t ah[4];
                const uint32_t aa = st + a_loff + (uint32_t)(mf * 16 * SA * 2) + (uint32_t)(ks * 32);
                LDSM4(ah[0], ah[1], ah[2], ah[3], aa);
                #pragma unroll
                for (int nf = 0; nf < 4; nf++) {
                    mma16(accG[mf][nf], ah, bGh[nf]);
                    if (FUSED) mma16(accU[mf][nf], ah, bUh[nf]);
                }
            }
        }
        CP_WAIT1();
        __syncthreads();
    }

    // ---- epilogue ----
    #pragma unroll
    for (int mf = 0; mf < 4; mf++) {
        #pragma unroll
        for (int h = 0; h < 2; h++) {
            int r = m0 + wm * 64 + mf * 16 + lg + h * 8;
            if (r >= ne) continue;
            int col = n0 + wn * 32 + lt * 2;
            if (FUSED) {
                size_t base = (size_t)(off + r) * INTER + col;
                #pragma unroll
                for (int nf = 0; nf < 4; nf++) {
                    float g0 = accG[mf][nf][2*h],   g1 = accG[mf][nf][2*h+1];
                    float u0 = accU[mf][nf][2*h],   u1 = accU[mf][nf][2*h+1];
                    float h0 = g0 * sigmoidf_fast(g0) * u0;
                    float h1 = g1 * sigmoidf_fast(g1) * u1;
                    *(uint32_t*)(g_hh + base + nf * 8) = cvt2h(h0, h1);
                }
            } else {
                float* orow = g_y + (size_t)(off + r) * HIDDEN + col;
                #pragma unroll
                for (int nf = 0; nf < 4; nf++) {
                    float2 v = make_float2(accG[mf][nf][2*h], accG[mf][nf][2*h+1]);
                    *(float2*)(orow + nf * 8) = v;
                }
            }
        }
    }
}

// ---------------- combine ----------------
__global__ void combine_kernel(float* __restrict__ out) {
    int idx = blockIdx.x * blockDim.x + threadIdx.x;
    int t = idx / (HIDDEN / 4);
    int c = idx % (HIDDEN / 4);
    int e0 = g_te[2*t], e1 = g_te[2*t+1];
    size_t p0 = (size_t)g_off[e0] + g_tslot[2*t];
    size_t p1 = (size_t)g_off[e1] + g_tslot[2*t+1];
    float w0 = g_tw[2*t], w1 = g_tw[2*t+1];
    float4 y0 = *(const float4*)(g_y + p0 * HIDDEN + 4*c);
    float4 y1 = *(const float4*)(g_y + p1 * HIDDEN + 4*c);
    float4 r;
    r.x = w0*y0.x + w1*y1.x; r.y = w0*y0.y + w1*y1.y;
    r.z = w0*y0.z + w1*y1.z; r.w = w0*y0.w + w1*y1.w;
    *(float4*)(out + (size_t)t * HIDDEN + 4*c) = r;
}

// ---------------- launcher ----------------
extern "C" void kernel_launch(void* const* d_in, const int* in_sizes, int n_in,
                              void* d_out, int out_size) {
    const float* X   = (const float*)d_in[0];
    const float* Wg  = (const float*)d_in[1];
    const float* Wgp = (const float*)d_in[2];
    const float* Wup = (const float*)d_in[3];
    const float* Wdp = (const float*)d_in[4];
    float* out = (float*)d_out;

    __half *xh, *w0h, *w1h, *wdh, *hh;
    cudaGetSymbolAddress((void**)&xh,  c_Xh);
    cudaGetSymbolAddress((void**)&w0h, c_W0h);
    cudaGetSymbolAddress((void**)&w1h, c_W1h);
    cudaGetSymbolAddress((void**)&wdh, c_Wdh);
    cudaGetSymbolAddress((void**)&hh,  g_hh);

    constexpr int STAGE_F = (128*40 + 2*32*136) * 2;   // 27648 B
    constexpr int STAGE_D = (128*40 + 1*32*136) * 2;   // 18944 B
    const int SMEM_F = 3 * STAGE_F;                    // 82944
    const int SMEM_D = 3 * STAGE_D;                    // 56832
    cudaFuncSetAttribute(moe_gemm_fp16<1>, cudaFuncAttributeMaxDynamicSharedMemorySize, SMEM_F);
    cudaFuncSetAttribute(moe_gemm_fp16<0>, cudaFuncAttributeMaxDynamicSharedMemorySize, SMEM_D);

    // ONE aux stream (R9-proven footprint) + lightweight events
    constexpr int NCH = 4;                 // expert chunks for gate/up pipeline
    static cudaStream_t sAux = nullptr;
    static cudaEvent_t  evFork = nullptr, evX = nullptr, evWd = nullptr;
    static cudaEvent_t  evW[NCH];
    if (sAux == nullptr) {
        cudaStreamCreateWithFlags(&sAux, cudaStreamNonBlocking);
        cudaEventCreateWithFlags(&evFork, cudaEventDisableTiming);
        cudaEventCreateWithFlags(&evX,    cudaEventDisableTiming);
        cudaEventCreateWithFlags(&evWd,   cudaEventDisableTiming);
        for (int c = 0; c < NCH; c++) cudaEventCreateWithFlags(&evW[c], cudaEventDisableTiming);
    }

    const int NX  = TOKENS * HIDDEN / 8;
    const int NW  = EXPERTS * HIDDEN * INTER / 8;
    const int NWC = NW / NCH;
    const size_t WCH = (size_t)(EXPERTS / NCH) * HIDDEN * INTER;   // floats per chunk

    // ---- fork aux off the main (capture) stream ----
    cudaEventRecord(evFork, 0);
    cudaStreamWaitEvent(sAux, evFork, 0);

    // aux: router -> cvt X -> chunked gate/up cvt -> Wd cvt   (main stays GEMM-only)
    zero_cnt_kernel<<<1, 32, 0, sAux>>>();
    router_logits_kernel<<<(TOKENS * EXPERTS) / 256, 256, 0, sAux>>>(X, Wg);
    router_topk_kernel<<<(TOKENS + 255) / 256, 256, 0, sAux>>>();
    offsets_kernel<<<1, 1, 0, sAux>>>();
    cvt_kernel<<<(NX + 255) / 256, 256, 0, sAux>>>(X, xh, NX);
    cudaEventRecord(evX, sAux);
    for (int c = 0; c < NCH; c++) {
        cvt_kernel<<<(NWC + 255) / 256, 256, 0, sAux>>>(Wgp + c * WCH, w0h + c * WCH, NWC);
        cvt_kernel<<<(NWC + 255) / 256, 256, 0, sAux>>>(Wup + c * WCH, w1h + c * WCH, NWC);
        cudaEventRecord(evW[c], sAux);
    }
    cvt_kernel<<<(NW + 255) / 256, 256, 0, sAux>>>(Wdp, wdh, NW);
    cudaEventRecord(evWd, sAux);

    // main: fused GEMM per chunk as soon as its weights are converted
    dim3 grid_f(TOKENS / 128, INTER / 128, EXPERTS / NCH);   // (16, 11, 4)
    cudaStreamWaitEvent(0, evX, 0);
    for (int c = 0; c < NCH; c++) {
        cudaStreamWaitEvent(0, evW[c], 0);
        moe_gemm_fp16<1><<<grid_f, 256, SMEM_F>>>(xh, w0h, w1h, c * (EXPERTS / NCH));
    }

    // main: down GEMM (needs all g_hh via stream order + wdh via event)
    cudaStreamWaitEvent(0, evWd, 0);
    dim3 grid_d(TOKENS / 128, HIDDEN / 128, EXPERTS);        // (16, 16, 16)
    moe_gemm_fp16<0><<<grid_d, 256, SMEM_D>>>(hh, wdh, nullptr, 0);

    combine_kernel<<<(TOKENS * (HIDDEN / 4)) / 256, 256>>>(out);
}

// round 12
// speedup vs baseline: 1.0266x; 1.0266x over previous
#include <cuda_runtime.h>
#include <cuda_fp16.h>
#include <cstdint>
#include <math.h>

#define TOKENS  2048
#define HIDDEN  2048
#define INTER   1408
#define EXPERTS 16
#define MAXPAIRS (TOKENS*2)

// ---------------- scratch ----------------
__device__ int   g_cnt[EXPERTS];
__device__ int   g_off[EXPERTS + 1];
__device__ int   g_tok[EXPERTS * TOKENS];
__device__ int   g_te[MAXPAIRS];
__device__ int   g_tslot[MAXPAIRS];
__device__ float g_tw[MAXPAIRS];
__device__ float g_logits[TOKENS * EXPERTS];
__device__ float g_y[(size_t)MAXPAIRS * HIDDEN];

// fp16 operands (single-term)
__device__ __half c_Xh[(size_t)TOKENS * HIDDEN];
__device__ __half c_W0h[(size_t)EXPERTS * HIDDEN * INTER];
__device__ __half c_W1h[(size_t)EXPERTS * HIDDEN * INTER];
__device__ __half c_Wdh[(size_t)EXPERTS * INTER * HIDDEN];
__device__ __half g_hh[(size_t)(MAXPAIRS + 128) * INTER];

// ---------------- helpers ----------------
__device__ __forceinline__ float sigmoidf_fast(float x) { return 1.0f / (1.0f + __expf(-x)); }

__device__ __forceinline__ uint32_t smem_u32(const void* p) {
    uint32_t a;
    asm("{ .reg .u64 t; cvta.to.shared.u64 t, %1; cvt.u32.u64 %0, t; }" : "=r"(a) : "l"(p));
    return a;
}
__device__ __forceinline__ uint32_t cvt2h(float x, float y) {
    __half2 h = __floats2half2_rn(x, y);
    return *(uint32_t*)&h;
}
// m16n8k16 fp16 MMA, fp32 accum
__device__ __forceinline__ void mma16(float* d, const uint32_t* a, const uint32_t* b) {
    asm volatile("mma.sync.aligned.m16n8k16.row.col.f32.f16.f16.f32 "
        "{%0,%1,%2,%3}, {%4,%5,%6,%7}, {%8,%9}, {%0,%1,%2,%3};"
        : "+f"(d[0]), "+f"(d[1]), "+f"(d[2]), "+f"(d[3])
        : "r"(a[0]), "r"(a[1]), "r"(a[2]), "r"(a[3]), "r"(b[0]), "r"(b[1]));
}
#define LDSM4(r0,r1,r2,r3,addr) \
    asm volatile("ldmatrix.sync.aligned.m8n8.x4.shared.b16 {%0,%1,%2,%3}, [%4];" \
        : "=r"(r0), "=r"(r1), "=r"(r2), "=r"(r3) : "r"(addr))
#define LDSM4T(r0,r1,r2,r3,addr) \
    asm volatile("ldmatrix.sync.aligned.m8n8.x4.trans.shared.b16 {%0,%1,%2,%3}, [%4];" \
        : "=r"(r0), "=r"(r1), "=r"(r2), "=r"(r3) : "r"(addr))
#define CP16(dst, src, sz) \
    asm volatile("cp.async.cg.shared.global [%0], [%1], 16, %2;" \
        :: "r"(dst), "l"(src), "r"(sz) : "memory")
#define CP_COMMIT() asm volatile("cp.async.commit_group;" ::: "memory")
#define CP_WAIT1()  asm volatile("cp.async.wait_group 1;" ::: "memory")

// ---------------- conversion: fp32 -> fp16 ----------------
__global__ void cvt_kernel(const float* __restrict__ src,
                           __half* __restrict__ dst, int n8) {
    int i = blockIdx.x * blockDim.x + threadIdx.x;
    if (i >= n8) return;
    const float4* s = (const float4*)src + 2 * (size_t)i;
    float4 v0 = s[0], v1 = s[1];
    *(uint4*)(dst + 8 * (size_t)i) = make_uint4(
        cvt2h(v0.x, v0.y), cvt2h(v0.z, v0.w), cvt2h(v1.x, v1.y), cvt2h(v1.z, v1.w));
}

// ---------------- routing (proven) ----------------
__global__ void zero_cnt_kernel() { if (threadIdx.x < EXPERTS) g_cnt[threadIdx.x] = 0; }

__global__ void router_logits_kernel(const float* __restrict__ X, const float* __restrict__ Wg) {
    int idx = blockIdx.x * blockDim.x + threadIdx.x;
    int t = idx >> 4, e = idx & 15;
    const float* xr = X + (size_t)t * HIDDEN;
    float s0 = 0.f, s1 = 0.f, s2 = 0.f, s3 = 0.f;
    #pragma unroll 4
    for (int k = 0; k < HIDDEN; k += 4) {
        s0 = fmaf(xr[k+0], Wg[(k+0)*EXPERTS + e], s0);
        s1 = fmaf(xr[k+1], Wg[(k+1)*EXPERTS + e], s1);
        s2 = fmaf(xr[k+2], Wg[(k+2)*EXPERTS + e], s2);
        s3 = fmaf(xr[k+3], Wg[(k+3)*EXPERTS + e], s3);
    }
    g_logits[idx] = (s0 + s1) + (s2 + s3);
}

__global__ void router_topk_kernel() {
    int t = blockIdx.x * blockDim.x + threadIdx.x;
    if (t >= TOKENS) return;
    float l[EXPERTS];
    #pragma unroll
    for (int e = 0; e < EXPERTS; e++) l[e] = g_logits[t * EXPERTS + e];
    int e1 = 0; float v1 = l[0];
    #pragma unroll
    for (int e = 1; e < EXPERTS; e++) if (l[e] > v1) { v1 = l[e]; e1 = e; }
    int e2 = -1; float v2 = -3.4e38f;
    #pragma unroll
    for (int e = 0; e < EXPERTS; e++) { if (e == e1) continue; if (l[e] > v2) { v2 = l[e]; e2 = e; } }
    float w1 = sigmoidf_fast(v1), w2 = sigmoidf_fast(v2);
    float inv = 1.0f / (w1 + w2); w1 *= inv; w2 *= inv;
    int s1 = atomicAdd(&g_cnt[e1], 1);
    int s2 = atomicAdd(&g_cnt[e2], 1);
    g_tok[e1 * TOKENS + s1] = t;
    g_tok[e2 * TOKENS + s2] = t;
    g_te[2*t+0] = e1; g_tslot[2*t+0] = s1; g_tw[2*t+0] = w1;
    g_te[2*t+1] = e2; g_tslot[2*t+1] = s2; g_tw[2*t+1] = w2;
}

__global__ void offsets_kernel() {
    if (threadIdx.x == 0 && blockIdx.x == 0) {
        int a = 0;
        for (int e = 0; e < EXPERTS; e++) { g_off[e] = a; a += g_cnt[e]; }
        g_off[EXPERTS] = a;
    }
}

// ---------------- fp16 single-term mma.sync grouped GEMM, cp.async 3-stage ----------------
// FUSED=1: A = gathered Xh rows; B0=W0h(gate), B1=W1h(up); epi h=silu(g)*u -> g_hh (fp16)
// FUSED=0: A = g_hh rows;        B0=Wdh;                   epi raw -> g_y (fp32)
// ebase: first expert of this launch (expert id = ebase + blockIdx.z)
template <int FUSED>
__global__ __launch_bounds__(256, 1)
void moe_gemm_fp16(const __half* __restrict__ Agh,
                   const __half* __restrict__ B0h_g,
                   const __half* __restrict__ B1h_g,
                   int ebase) {
    constexpr int Kdim = FUSED ? HIDDEN : INTER;
    constexpr int Ndim = FUSED ? INTER : HIDDEN;
    constexpr int KT   = Kdim / 32;
    constexpr int SA   = 40;   // halves
    constexpr int SB   = 136;  // halves
    constexpr int B0H  = 128 * SA;          // 5120
    constexpr int B1H  = B0H + 32 * SB;
    constexpr int STAGE_H = B0H + (FUSED ? 2 : 1) * 32 * SB;
    constexpr int STAGE_B = STAGE_H * 2;

    const int e  = ebase + blockIdx.z;
    const int ne = g_cnt[e];
    const int m0 = blockIdx.x * 128;
    if (m0 >= ne) return;
    const int n0  = blockIdx.y * 128;
    const int off = g_off[e];

    extern __shared__ __align__(16) uint16_t smh[];
    const uint32_t sbase = smem_u32(smh);

    const int tid  = threadIdx.x;
    const int lane = tid & 31;
    const int wid  = tid >> 5;
    const int wm   = wid & 1;
    const int wn   = wid >> 1;
    const int lg   = lane >> 2;
    const int lt   = lane & 3;
    const int q    = lane >> 3;
    const int rr   = lane & 7;

    const uint32_t a_loff = (uint32_t)(((wm * 64 + (q & 1) * 8 + rr) * SA + (q >> 1) * 8) * 2);
    const uint32_t b_loff = (uint32_t)((rr * SB + wn * 32 + q * 8) * 2);

    // A: thread covers row (tid>>1), halves [(tid&1)*16, +16)
    const int ar  = tid >> 1;
    const int ach = (tid & 1) * 16;
    const __half* pAh;
    uint32_t aSz;
    {
        int r = m0 + ar;
        if (FUSED) {
            if (r < ne) {
                pAh = Agh + (size_t)g_tok[e * TOKENS + r] * Kdim + ach; aSz = 16;
            } else { pAh = Agh; aSz = 0; }
        } else {
            pAh = Agh + (size_t)(off + r) * Kdim + ach; aSz = 16;
        }
    }
    const uint32_t dA = (uint32_t)((ar * SA + ach) * 2);
    // B: thread covers k-row (tid>>3), halves [(tid&7)*16, +16)
    const int br  = tid >> 3;
    const int bch = (tid & 7) * 16;
    const size_t bstart = (size_t)e * Kdim * Ndim + (size_t)br * Ndim + n0 + bch;
    const __half* pB0h = B0h_g + bstart;
    const __half* pB1h = FUSED ? (B1h_g + bstart) : nullptr;
    const uint32_t dB = (uint32_t)((br * SB + bch) * 2);

    auto issue = [&](int kt, int buf) {
        const uint32_t st = sbase + (uint32_t)buf * STAGE_B;
        const size_t ak = (size_t)kt * 32;
        const size_t bk = (size_t)kt * 32 * Ndim;
        CP16(st + dA,                 pAh + ak,      aSz);
        CP16(st + dA + 16,            pAh + ak + 8,  aSz);
        CP16(st + dB + B0H * 2,       pB0h + bk,     16u);
        CP16(st + dB + B0H * 2 + 16,  pB0h + bk + 8, 16u);
        if (FUSED) {
            CP16(st + dB + B1H * 2,       pB1h + bk,     16u);
            CP16(st + dB + B1H * 2 + 16,  pB1h + bk + 8, 16u);
        }
    };

    float accG[4][4][4];
    float accU[FUSED ? 4 : 1][4][4];
    #pragma unroll
    for (int i = 0; i < 4; i++)
        #pragma unroll
        for (int j = 0; j < 4; j++)
            #pragma unroll
            for (int p = 0; p < 4; p++) { accG[i][j][p] = 0.f; if (FUSED) accU[i][j][p] = 0.f; }

    issue(0, 0); CP_COMMIT();
    if (KT > 1) issue(1, 1);
    CP_COMMIT();
    CP_WAIT1();
    __syncthreads();

    for (int kt = 0; kt < KT; kt++) {
        if (kt + 2 < KT) issue(kt + 2, (kt + 2) % 3);
        CP_COMMIT();

        const uint32_t st = sbase + (uint32_t)(kt % 3) * STAGE_B;
        #pragma unroll
        for (int ks = 0; ks < 2; ks++) {
            const uint32_t bks = (uint32_t)(ks * 16 * SB * 2);
            uint32_t bGh[4][2];
            uint32_t bUh[FUSED ? 4 : 1][2];
            {
                uint32_t t0, t1, t2, t3;
                uint32_t ba = st + (uint32_t)(B0H * 2) + b_loff + bks;
                LDSM4T(t0, t1, t2, t3, ba);
                bGh[0][0]=t0; bGh[1][0]=t1; bGh[2][0]=t2; bGh[3][0]=t3;
                LDSM4T(t0, t1, t2, t3, ba + 8 * SB * 2);
                bGh[0][1]=t0; bGh[1][1]=t1; bGh[2][1]=t2; bGh[3][1]=t3;
                if (FUSED) {
                    ba = st + (uint32_t)(B1H * 2) + b_loff + bks;
                    LDSM4T(t0, t1, t2, t3, ba);
                    bUh[0][0]=t0; bUh[1][0]=t1; bUh[2][0]=t2; bUh[3][0]=t3;
                    LDSM4T(t0, t1, t2, t3, ba + 8 * SB * 2);
                    bUh[0][1]=t0; bUh[1][1]=t1; bUh[2][1]=t2; bUh[3][1]=t3;
                }
            }
            #pragma unroll
            for (int mf = 0; mf < 4; mf++) {
                uint32_t ah[4];
                const uint32_t aa = st + a_loff + (uint32_t)(mf * 16 * SA * 2) + (uint32_t)(ks * 32);
                LDSM4(ah[0], ah[1], ah[2], ah[3], aa);
                #pragma unroll
                for (int nf = 0; nf < 4; nf++) {
                    mma16(accG[mf][nf], ah, bGh[nf]);
                    if (FUSED) mma16(accU[mf][nf], ah, bUh[nf]);
                }
            }
        }
        CP_WAIT1();
        __syncthreads();
    }

    // ---- epilogue ----
    #pragma unroll
    for (int mf = 0; mf < 4; mf++) {
        #pragma unroll
        for (int h = 0; h < 2; h++) {
            int r = m0 + wm * 64 + mf * 16 + lg + h * 8;
            if (r >= ne) continue;
            int col = n0 + wn * 32 + lt * 2;
            if (FUSED) {
                size_t base = (size_t)(off + r) * INTER + col;
                #pragma unroll
                for (int nf = 0; nf < 4; nf++) {
                    float g0 = accG[mf][nf][2*h],   g1 = accG[mf][nf][2*h+1];
                    float u0 = accU[mf][nf][2*h],   u1 = accU[mf][nf][2*h+1];
                    float h0 = g0 * sigmoidf_fast(g0) * u0;
                    float h1 = g1 * sigmoidf_fast(g1) * u1;
                    *(uint32_t*)(g_hh + base + nf * 8) = cvt2h(h0, h1);
                }
            } else {
                float* orow = g_y + (size_t)(off + r) * HIDDEN + col;
                #pragma unroll
                for (int nf = 0; nf < 4; nf++) {
                    float2 v = make_float2(accG[mf][nf][2*h], accG[mf][nf][2*h+1]);
                    *(float2*)(orow + nf * 8) = v;
                }
            }
        }
    }
}

// ---------------- combine ----------------
__global__ void combine_kernel(float* __restrict__ out) {
    int idx = blockIdx.x * blockDim.x + threadIdx.x;
    int t = idx / (HIDDEN / 4);
    int c = idx % (HIDDEN / 4);
    int e0 = g_te[2*t], e1 = g_te[2*t+1];
    size_t p0 = (size_t)g_off[e0] + g_tslot[2*t];
    size_t p1 = (size_t)g_off[e1] + g_tslot[2*t+1];
    float w0 = g_tw[2*t], w1 = g_tw[2*t+1];
    float4 y0 = *(const float4*)(g_y + p0 * HIDDEN + 4*c);
    float4 y1 = *(const float4*)(g_y + p1 * HIDDEN + 4*c);
    float4 r;
    r.x = w0*y0.x + w1*y1.x; r.y = w0*y0.y + w1*y1.y;
    r.z = w0*y0.z + w1*y1.z; r.w = w0*y0.w + w1*y1.w;
    *(float4*)(out + (size_t)t * HIDDEN + 4*c) = r;
}

// ---------------- launcher ----------------
extern "C" void kernel_launch(void* const* d_in, const int* in_sizes, int n_in,
                              void* d_out, int out_size) {
    const float* X   = (const float*)d_in[0];
    const float* Wg  = (const float*)d_in[1];
    const float* Wgp = (const float*)d_in[2];
    const float* Wup = (const float*)d_in[3];
    const float* Wdp = (const float*)d_in[4];
    float* out = (float*)d_out;

    __half *xh, *w0h, *w1h, *wdh, *hh;
    cudaGetSymbolAddress((void**)&xh,  c_Xh);
    cudaGetSymbolAddress((void**)&w0h, c_W0h);
    cudaGetSymbolAddress((void**)&w1h, c_W1h);
    cudaGetSymbolAddress((void**)&wdh, c_Wdh);
    cudaGetSymbolAddress((void**)&hh,  g_hh);

    constexpr int STAGE_F = (128*40 + 2*32*136) * 2;   // 27648 B
    constexpr int STAGE_D = (128*40 + 1*32*136) * 2;   // 18944 B
    const int SMEM_F = 3 * STAGE_F;                    // 82944
    const int SMEM_D = 3 * STAGE_D;                    // 56832
    cudaFuncSetAttribute(moe_gemm_fp16<1>, cudaFuncAttributeMaxDynamicSharedMemorySize, SMEM_F);
    cudaFuncSetAttribute(moe_gemm_fp16<0>, cudaFuncAttributeMaxDynamicSharedMemorySize, SMEM_D);

    // ONE aux stream + 4 events (R9-proven footprint + 1 event)
    static cudaStream_t sAux = nullptr;
    static cudaEvent_t  evFork = nullptr, evX = nullptr, evW1 = nullptr, evWd = nullptr;
    if (sAux == nullptr) {
        cudaStreamCreateWithFlags(&sAux, cudaStreamNonBlocking);
        cudaEventCreateWithFlags(&evFork, cudaEventDisableTiming);
        cudaEventCreateWithFlags(&evX,    cudaEventDisableTiming);
        cudaEventCreateWithFlags(&evW1,   cudaEventDisableTiming);
        cudaEventCreateWithFlags(&evWd,   cudaEventDisableTiming);
    }

    const int NX  = TOKENS * HIDDEN / 8;
    const int NW  = EXPERTS * HIDDEN * INTER / 8;
    const int NWH = NW / 2;                                   // half the experts
    const size_t WCH = (size_t)(EXPERTS / 2) * HIDDEN * INTER; // floats per half

    // ---- fork aux off the main (capture) stream ----
    cudaEventRecord(evFork, 0);
    cudaStreamWaitEvent(sAux, evFork, 0);

    // aux: router + X cvt, then second-half gate/up cvt (hides under fused chunk 0),
    //      then Wd cvt (hides under fused chunk 1)
    zero_cnt_kernel<<<1, 32, 0, sAux>>>();
    router_logits_kernel<<<(TOKENS * EXPERTS) / 256, 256, 0, sAux>>>(X, Wg);
    router_topk_kernel<<<(TOKENS + 255) / 256, 256, 0, sAux>>>();
    offsets_kernel<<<1, 1, 0, sAux>>>();
    cvt_kernel<<<(NX + 255) / 256, 256, 0, sAux>>>(X, xh, NX);
    cudaEventRecord(evX, sAux);
    cvt_kernel<<<(NWH + 255) / 256, 256, 0, sAux>>>(Wgp + WCH, w0h + WCH, NWH);
    cvt_kernel<<<(NWH + 255) / 256, 256, 0, sAux>>>(Wup + WCH, w1h + WCH, NWH);
    cudaEventRecord(evW1, sAux);
    cvt_kernel<<<(NW + 255) / 256, 256, 0, sAux>>>(Wdp, wdh, NW);
    cudaEventRecord(evWd, sAux);

    // main: first-half gate/up cvt starts at t=0 (R9 property)
    cvt_kernel<<<(NWH + 255) / 256, 256>>>(Wgp, w0h, NWH);
    cvt_kernel<<<(NWH + 255) / 256, 256>>>(Wup, w1h, NWH);

    // fused GEMM chunk 0 (experts 0..7)
    dim3 grid_f(TOKENS / 128, INTER / 128, EXPERTS / 2);   // (16, 11, 8)
    cudaStreamWaitEvent(0, evX, 0);
    moe_gemm_fp16<1><<<grid_f, 256, SMEM_F>>>(xh, w0h, w1h, 0);

    // fused GEMM chunk 1 (experts 8..15)
    cudaStreamWaitEvent(0, evW1, 0);
    moe_gemm_fp16<1><<<grid_f, 256, SMEM_F>>>(xh, w0h, w1h, EXPERTS / 2);

    // down GEMM (all experts; needs g_hh via stream order + wdh via event)
    cudaStreamWaitEvent(0, evWd, 0);
    dim3 grid_d(TOKENS / 128, HIDDEN / 128, EXPERTS);      // (16, 16, 16)
    moe_gemm_fp16<0><<<grid_d, 256, SMEM_D>>>(hh, wdh, nullptr, 0);

    combine_kernel<<<(TOKENS * (HIDDEN / 4)) / 256, 256>>>(out);
}

// round 13
// speedup vs baseline: 1.1976x; 1.1666x over previous
#include <cuda_runtime.h>
#include <cuda_fp16.h>
#include <cstdint>
#include <math.h>

#define TOKENS  2048
#define HIDDEN  2048
#define INTER   1408
#define EXPERTS 16
#define MAXPAIRS (TOKENS*2)

// ---------------- scratch ----------------
__device__ int   g_cnt[EXPERTS];
__device__ int   g_off[EXPERTS + 1];
__device__ int   g_tok[EXPERTS * TOKENS];
__device__ int   g_te[MAXPAIRS];
__device__ int   g_tslot[MAXPAIRS];
__device__ float g_tw[MAXPAIRS];
__device__ float g_logits[TOKENS * EXPERTS];
__device__ float g_y[(size_t)MAXPAIRS * HIDDEN];

// fp16 operands (single-term)
__device__ __half c_Xh[(size_t)TOKENS * HIDDEN];
__device__ __half c_W0h[(size_t)EXPERTS * HIDDEN * INTER];
__device__ __half c_W1h[(size_t)EXPERTS * HIDDEN * INTER];
__device__ __half c_Wdh[(size_t)EXPERTS * INTER * HIDDEN];
__device__ __half g_hh[(size_t)(MAXPAIRS + 128) * INTER];

// ---------------- helpers ----------------
__device__ __forceinline__ float sigmoidf_fast(float x) { return 1.0f / (1.0f + __expf(-x)); }

__device__ __forceinline__ uint32_t smem_u32(const void* p) {
    uint32_t a;
    asm("{ .reg .u64 t; cvta.to.shared.u64 t, %1; cvt.u32.u64 %0, t; }" : "=r"(a) : "l"(p));
    return a;
}
__device__ __forceinline__ uint32_t cvt2h(float x, float y) {
    __half2 h = __floats2half2_rn(x, y);
    return *(uint32_t*)&h;
}
// m16n8k16 fp16 MMA, fp32 accum
__device__ __forceinline__ void mma16(float* d, const uint32_t* a, const uint32_t* b) {
    asm volatile("mma.sync.aligned.m16n8k16.row.col.f32.f16.f16.f32 "
        "{%0,%1,%2,%3}, {%4,%5,%6,%7}, {%8,%9}, {%0,%1,%2,%3};"
        : "+f"(d[0]), "+f"(d[1]), "+f"(d[2]), "+f"(d[3])
        : "r"(a[0]), "r"(a[1]), "r"(a[2]), "r"(a[3]), "r"(b[0]), "r"(b[1]));
}
#define LDSM4(r0,r1,r2,r3,addr) \
    asm volatile("ldmatrix.sync.aligned.m8n8.x4.shared.b16 {%0,%1,%2,%3}, [%4];" \
        : "=r"(r0), "=r"(r1), "=r"(r2), "=r"(r3) : "r"(addr))
#define LDSM4T(r0,r1,r2,r3,addr) \
    asm volatile("ldmatrix.sync.aligned.m8n8.x4.trans.shared.b16 {%0,%1,%2,%3}, [%4];" \
        : "=r"(r0), "=r"(r1), "=r"(r2), "=r"(r3) : "r"(addr))
#define CP16(dst, src, sz) \
    asm volatile("cp.async.cg.shared.global [%0], [%1], 16, %2;" \
        :: "r"(dst), "l"(src), "r"(sz) : "memory")
#define CP_COMMIT() asm volatile("cp.async.commit_group;" ::: "memory")
#define CP_WAIT1()  asm volatile("cp.async.wait_group 1;" ::: "memory")

// ---------------- conversion: fp32 -> fp16 ----------------
__global__ void cvt_kernel(const float* __restrict__ src,
                           __half* __restrict__ dst, int n8) {
    int i = blockIdx.x * blockDim.x + threadIdx.x;
    if (i >= n8) return;
    const float4* s = (const float4*)src + 2 * (size_t)i;
    float4 v0 = s[0], v1 = s[1];
    *(uint4*)(dst + 8 * (size_t)i) = make_uint4(
        cvt2h(v0.x, v0.y), cvt2h(v0.z, v0.w), cvt2h(v1.x, v1.y), cvt2h(v1.z, v1.w));
}

// ---------------- routing (proven) ----------------
__global__ void zero_cnt_kernel() { if (threadIdx.x < EXPERTS) g_cnt[threadIdx.x] = 0; }

__global__ void router_logits_kernel(const float* __restrict__ X, const float* __restrict__ Wg) {
    int idx = blockIdx.x * blockDim.x + threadIdx.x;
    int t = idx >> 4, e = idx & 15;
    const float* xr = X + (size_t)t * HIDDEN;
    float s0 = 0.f, s1 = 0.f, s2 = 0.f, s3 = 0.f;
    #pragma unroll 4
    for (int k = 0; k < HIDDEN; k += 4) {
        s0 = fmaf(xr[k+0], Wg[(k+0)*EXPERTS + e], s0);
        s1 = fmaf(xr[k+1], Wg[(k+1)*EXPERTS + e], s1);
        s2 = fmaf(xr[k+2], Wg[(k+2)*EXPERTS + e], s2);
        s3 = fmaf(xr[k+3], Wg[(k+3)*EXPERTS + e], s3);
    }
    g_logits[idx] = (s0 + s1) + (s2 + s3);
}

__global__ void router_topk_kernel() {
    int t = blockIdx.x * blockDim.x + threadIdx.x;
    if (t >= TOKENS) return;
    float l[EXPERTS];
    #pragma unroll
    for (int e = 0; e < EXPERTS; e++) l[e] = g_logits[t * EXPERTS + e];
    int e1 = 0; float v1 = l[0];
    #pragma unroll
    for (int e = 1; e < EXPERTS; e++) if (l[e] > v1) { v1 = l[e]; e1 = e; }
    int e2 = -1; float v2 = -3.4e38f;
    #pragma unroll
    for (int e = 0; e < EXPERTS; e++) { if (e == e1) continue; if (l[e] > v2) { v2 = l[e]; e2 = e; } }
    float w1 = sigmoidf_fast(v1), w2 = sigmoidf_fast(v2);
    float inv = 1.0f / (w1 + w2); w1 *= inv; w2 *= inv;
    int s1 = atomicAdd(&g_cnt[e1], 1);
    int s2 = atomicAdd(&g_cnt[e2], 1);
    g_tok[e1 * TOKENS + s1] = t;
    g_tok[e2 * TOKENS + s2] = t;
    g_te[2*t+0] = e1; g_tslot[2*t+0] = s1; g_tw[2*t+0] = w1;
    g_te[2*t+1] = e2; g_tslot[2*t+1] = s2; g_tw[2*t+1] = w2;
}

__global__ void offsets_kernel() {
    if (threadIdx.x == 0 && blockIdx.x == 0) {
        int a = 0;
        for (int e = 0; e < EXPERTS; e++) { g_off[e] = a; a += g_cnt[e]; }
        g_off[EXPERTS] = a;
    }
}

// ---------------- fp16 single-term mma.sync grouped GEMM ----------------
// CTA tile 128x64, BK=32, 8 warps (2m x 4n), warp tile 64x16, 2 CTAs/SM.
// FUSED=1: A = gathered Xh rows; B0=W0h(gate), B1=W1h(up); epi h=silu(g)*u -> g_hh (fp16)
// FUSED=0: A = g_hh rows;        B0=Wdh;                   epi raw -> g_y (fp32)
template <int FUSED>
__global__ __launch_bounds__(256, 2)
void moe_gemm_fp16(const __half* __restrict__ Agh,
                   const __half* __restrict__ B0h_g,
                   const __half* __restrict__ B1h_g,
                   int ebase) {
    constexpr int Kdim = FUSED ? HIDDEN : INTER;
    constexpr int Ndim = FUSED ? INTER : HIDDEN;
    constexpr int KT   = Kdim / 32;
    constexpr int SA   = 40;   // A row stride (halves)
    constexpr int SB   = 72;   // B k-row stride (halves), 64 data + 8 pad
    constexpr int B0H  = 128 * SA;           // 5120 halves
    constexpr int B1H  = B0H + 32 * SB;      // 7424
    constexpr int STAGE_H = B0H + (FUSED ? 2 : 1) * 32 * SB;
    constexpr int STAGE_B = STAGE_H * 2;

    const int e  = ebase + blockIdx.z;
    const int ne = g_cnt[e];
    const int m0 = blockIdx.x * 128;
    if (m0 >= ne) return;
    const int n0  = blockIdx.y * 64;
    const int off = g_off[e];

    extern __shared__ __align__(16) uint16_t smh[];
    const uint32_t sbase = smem_u32(smh);

    const int tid  = threadIdx.x;
    const int lane = tid & 31;
    const int wid  = tid >> 5;
    const int wm   = wid & 1;        // m block 0/64
    const int wn   = wid >> 1;       // n block *16
    const int lg   = lane >> 2;
    const int lt   = lane & 3;
    const int q    = lane >> 3;      // ldmatrix matrix id 0..3
    const int rr   = lane & 7;       // ldmatrix row id

    // A ldmatrix: q0 (m0-7,k0-7), q1 (m8-15,k0-7), q2 (m0-7,k8-15), q3 (m8-15,k8-15)
    const uint32_t a_loff = (uint32_t)(((wm * 64 + (q & 1) * 8 + rr) * SA + (q >> 1) * 8) * 2);
    // B ldmatrix (trans): q0 (k0-7,n0-7), q1 (k8-15,n0-7), q2 (k0-7,n8-15), q3 (k8-15,n8-15)
    const uint32_t b_loff = (uint32_t)((((q & 1) * 8 + rr) * SB + wn * 16 + (q >> 1) * 8) * 2);

    // A cp.async: thread covers row (tid>>1), halves [(tid&1)*16, +16)
    const int ar  = tid >> 1;
    const int ach = (tid & 1) * 16;
    const __half* pAh;
    uint32_t aSz;
    {
        int r = m0 + ar;
        if (FUSED) {
            if (r < ne) {
                pAh = Agh + (size_t)g_tok[e * TOKENS + r] * Kdim + ach; aSz = 16;
            } else { pAh = Agh; aSz = 0; }
        } else {
            pAh = Agh + (size_t)(off + r) * Kdim + ach; aSz = 16;
        }
    }
    const uint32_t dA = (uint32_t)((ar * SA + ach) * 2);
    // B cp.async: thread covers k-row (tid>>3), halves [(tid&7)*8, +8) (16B)
    const int br  = tid >> 3;
    const int bch = (tid & 7) * 8;
    const size_t bstart = (size_t)e * Kdim * Ndim + (size_t)br * Ndim + n0 + bch;
    const __half* pB0h = B0h_g + bstart;
    const __half* pB1h = FUSED ? (B1h_g + bstart) : nullptr;
    const uint32_t dB = (uint32_t)((br * SB + bch) * 2);

    auto issue = [&](int kt, int buf) {
        const uint32_t st = sbase + (uint32_t)buf * STAGE_B;
        const size_t ak = (size_t)kt * 32;
        const size_t bk = (size_t)kt * 32 * Ndim;
        CP16(st + dA,                pAh + ak,     aSz);
        CP16(st + dA + 16,           pAh + ak + 8, aSz);
        CP16(st + dB + B0H * 2,      pB0h + bk,    16u);
        if (FUSED) CP16(st + dB + B1H * 2, pB1h + bk, 16u);
    };

    float accG[4][2][4];
    float accU[FUSED ? 4 : 1][2][4];
    #pragma unroll
    for (int i = 0; i < 4; i++)
        #pragma unroll
        for (int j = 0; j < 2; j++)
            #pragma unroll
            for (int p = 0; p < 4; p++) { accG[i][j][p] = 0.f; if (FUSED) accU[i][j][p] = 0.f; }

    issue(0, 0); CP_COMMIT();
    if (KT > 1) issue(1, 1);
    CP_COMMIT();
    CP_WAIT1();
    __syncthreads();

    for (int kt = 0; kt < KT; kt++) {
        if (kt + 2 < KT) issue(kt + 2, (kt + 2) % 3);
        CP_COMMIT();

        const uint32_t st = sbase + (uint32_t)(kt % 3) * STAGE_B;
        #pragma unroll
        for (int ks = 0; ks < 2; ks++) {
            const uint32_t bks = (uint32_t)(ks * 16 * SB * 2);
            // B fragments: one LDSM4T.x4 per matrix covers k16 x n16
            uint32_t bGh[2][2];
            uint32_t bUh[FUSED ? 2 : 1][2];
            {
                uint32_t t0, t1, t2, t3;
                LDSM4T(t0, t1, t2, t3, st + (uint32_t)(B0H * 2) + b_loff + bks);
                bGh[0][0]=t0; bGh[0][1]=t1; bGh[1][0]=t2; bGh[1][1]=t3;
                if (FUSED) {
                    LDSM4T(t0, t1, t2, t3, st + (uint32_t)(B1H * 2) + b_loff + bks);
                    bUh[0][0]=t0; bUh[0][1]=t1; bUh[1][0]=t2; bUh[1][1]=t3;
                }
            }
            #pragma unroll
            for (int mf = 0; mf < 4; mf++) {
                uint32_t ah[4];
                const uint32_t aa = st + a_loff + (uint32_t)(mf * 16 * SA * 2) + (uint32_t)(ks * 32);
                LDSM4(ah[0], ah[1], ah[2], ah[3], aa);
                #pragma unroll
                for (int nf = 0; nf < 2; nf++) {
                    mma16(accG[mf][nf], ah, bGh[nf]);
                    if (FUSED) mma16(accU[mf][nf], ah, bUh[nf]);
                }
            }
        }
        CP_WAIT1();
        __syncthreads();
    }

    // ---- epilogue ----
    #pragma unroll
    for (int mf = 0; mf < 4; mf++) {
        #pragma unroll
        for (int h = 0; h < 2; h++) {
            int r = m0 + wm * 64 + mf * 16 + lg + h * 8;
            if (r >= ne) continue;
            int col = n0 + wn * 16 + lt * 2;
            if (FUSED) {
                size_t base = (size_t)(off + r) * INTER + col;
                #pragma unroll
                for (int nf = 0; nf < 2; nf++) {
                    float g0 = accG[mf][nf][2*h],   g1 = accG[mf][nf][2*h+1];
                    float u0 = accU[mf][nf][2*h],   u1 = accU[mf][nf][2*h+1];
                    float h0 = g0 * sigmoidf_fast(g0) * u0;
                    float h1 = g1 * sigmoidf_fast(g1) * u1;
                    *(uint32_t*)(g_hh + base + nf * 8) = cvt2h(h0, h1);
                }
            } else {
                float* orow = g_y + (size_t)(off + r) * HIDDEN + col;
                #pragma unroll
                for (int nf = 0; nf < 2; nf++) {
                    float2 v = make_float2(accG[mf][nf][2*h], accG[mf][nf][2*h+1]);
                    *(float2*)(orow + nf * 8) = v;
                }
            }
        }
    }
}

// ---------------- combine ----------------
__global__ void combine_kernel(float* __restrict__ out) {
    int idx = blockIdx.x * blockDim.x + threadIdx.x;
    int t = idx / (HIDDEN / 4);
    int c = idx % (HIDDEN / 4);
    int e0 = g_te[2*t], e1 = g_te[2*t+1];
    size_t p0 = (size_t)g_off[e0] + g_tslot[2*t];
    size_t p1 = (size_t)g_off[e1] + g_tslot[2*t+1];
    float w0 = g_tw[2*t], w1 = g_tw[2*t+1];
    float4 y0 = *(const float4*)(g_y + p0 * HIDDEN + 4*c);
    float4 y1 = *(const float4*)(g_y + p1 * HIDDEN + 4*c);
    float4 r;
    r.x = w0*y0.x + w1*y1.x; r.y = w0*y0.y + w1*y1.y;
    r.z = w0*y0.z + w1*y1.z; r.w = w0*y0.w + w1*y1.w;
    *(float4*)(out + (size_t)t * HIDDEN + 4*c) = r;
}

// ---------------- launcher (R9-proven schedule) ----------------
extern "C" void kernel_launch(void* const* d_in, const int* in_sizes, int n_in,
                              void* d_out, int out_size) {
    const float* X   = (const float*)d_in[0];
    const float* Wg  = (const float*)d_in[1];
    const float* Wgp = (const float*)d_in[2];
    const float* Wup = (const float*)d_in[3];
    const float* Wdp = (const float*)d_in[4];
    float* out = (float*)d_out;

    __half *xh, *w0h, *w1h, *wdh, *hh;
    cudaGetSymbolAddress((void**)&xh,  c_Xh);
    cudaGetSymbolAddress((void**)&w0h, c_W0h);
    cudaGetSymbolAddress((void**)&w1h, c_W1h);
    cudaGetSymbolAddress((void**)&wdh, c_Wdh);
    cudaGetSymbolAddress((void**)&hh,  g_hh);

    constexpr int STAGE_F = (128*40 + 2*32*72) * 2;   // 19456 B
    constexpr int STAGE_D = (128*40 + 1*32*72) * 2;   // 14848 B
    const int SMEM_F = 3 * STAGE_F;                   // 58368
    const int SMEM_D = 3 * STAGE_D;                   // 44544
    cudaFuncSetAttribute(moe_gemm_fp16<1>, cudaFuncAttributeMaxDynamicSharedMemorySize, SMEM_F);
    cudaFuncSetAttribute(moe_gemm_fp16<0>, cudaFuncAttributeMaxDynamicSharedMemorySize, SMEM_D);

    // ONE aux stream + 3 events (R9-proven footprint)
    static cudaStream_t sAux = nullptr;
    static cudaEvent_t  evFork = nullptr, evX = nullptr, evWd = nullptr;
    if (sAux == nullptr) {
        cudaStreamCreateWithFlags(&sAux, cudaStreamNonBlocking);
        cudaEventCreateWithFlags(&evFork, cudaEventDisableTiming);
        cudaEventCreateWithFlags(&evX,    cudaEventDisableTiming);
        cudaEventCreateWithFlags(&evWd,   cudaEventDisableTiming);
    }

    const int NX = TOKENS * HIDDEN / 8;
    const int NW = EXPERTS * HIDDEN * INTER / 8;

    // ---- fork aux off the main (capture) stream ----
    cudaEventRecord(evFork, 0);
    cudaStreamWaitEvent(sAux, evFork, 0);

    // aux: routing + X conversion, then Wd conversion (overlaps fused GEMM)
    zero_cnt_kernel<<<1, 32, 0, sAux>>>();
    router_logits_kernel<<<(TOKENS * EXPERTS) / 256, 256, 0, sAux>>>(X, Wg);
    router_topk_kernel<<<(TOKENS + 255) / 256, 256, 0, sAux>>>();
    offsets_kernel<<<1, 1, 0, sAux>>>();
    cvt_kernel<<<(NX + 255) / 256, 256, 0, sAux>>>(X, xh, NX);
    cudaEventRecord(evX, sAux);
    cvt_kernel<<<(NW + 255) / 256, 256, 0, sAux>>>(Wdp, wdh, NW);
    cudaEventRecord(evWd, sAux);

    // main: gate/up weight conversion
    cvt_kernel<<<(NW + 255) / 256, 256>>>(Wgp, w0h, NW);
    cvt_kernel<<<(NW + 255) / 256, 256>>>(Wup, w1h, NW);

    // join: fused GEMM needs router + xh (+ w0h/w1h via stream order)
    cudaStreamWaitEvent(0, evX, 0);
    dim3 grid_f(TOKENS / 128, INTER / 64, EXPERTS);    // (16, 22, 16)
    moe_gemm_fp16<1><<<grid_f, 256, SMEM_F>>>(xh, w0h, w1h, 0);

    // join: down GEMM additionally needs wdh
    cudaStreamWaitEvent(0, evWd, 0);
    dim3 grid_d(TOKENS / 128, HIDDEN / 64, EXPERTS);   // (16, 32, 16)
    moe_gemm_fp16<0><<<grid_d, 256, SMEM_D>>>(hh, wdh, nullptr, 0);

    combine_kernel<<<(TOKENS * (HIDDEN / 4)) / 256, 256>>>(out);
}

// round 14
// speedup vs baseline: 1.2437x; 1.0385x over previous
#include <cuda_runtime.h>
#include <cuda_fp16.h>
#include <cstdint>
#include <math.h>

#define TOKENS  2048
#define HIDDEN  2048
#define INTER   1408
#define EXPERTS 16
#define MAXPAIRS (TOKENS*2)

// ---------------- scratch ----------------
__device__ int   g_cnt[EXPERTS];
__device__ int   g_off[EXPERTS + 1];
__device__ int   g_tok[EXPERTS * TOKENS];
__device__ int   g_te[MAXPAIRS];
__device__ int   g_tslot[MAXPAIRS];
__device__ float g_tw[MAXPAIRS];
__device__ float g_logits[TOKENS * EXPERTS];
__device__ float g_y[(size_t)MAXPAIRS * HIDDEN];

// fp16 operands (single-term)
__device__ __half c_Xh[(size_t)TOKENS * HIDDEN];
__device__ __half c_W0h[(size_t)EXPERTS * HIDDEN * INTER];
__device__ __half c_W1h[(size_t)EXPERTS * HIDDEN * INTER];
__device__ __half c_Wdh[(size_t)EXPERTS * INTER * HIDDEN];
__device__ __half g_hh[(size_t)(MAXPAIRS + 128) * INTER];

// ---------------- helpers ----------------
__device__ __forceinline__ float sigmoidf_fast(float x) { return 1.0f / (1.0f + __expf(-x)); }

__device__ __forceinline__ uint32_t smem_u32(const void* p) {
    uint32_t a;
    asm("{ .reg .u64 t; cvta.to.shared.u64 t, %1; cvt.u32.u64 %0, t; }" : "=r"(a) : "l"(p));
    return a;
}
__device__ __forceinline__ uint32_t cvt2h(float x, float y) {
    __half2 h = __floats2half2_rn(x, y);
    return *(uint32_t*)&h;
}
// m16n8k16 fp16 MMA, fp32 accum
__device__ __forceinline__ void mma16(float* d, const uint32_t* a, const uint32_t* b) {
    asm volatile("mma.sync.aligned.m16n8k16.row.col.f32.f16.f16.f32 "
        "{%0,%1,%2,%3}, {%4,%5,%6,%7}, {%8,%9}, {%0,%1,%2,%3};"
        : "+f"(d[0]), "+f"(d[1]), "+f"(d[2]), "+f"(d[3])
        : "r"(a[0]), "r"(a[1]), "r"(a[2]), "r"(a[3]), "r"(b[0]), "r"(b[1]));
}
#define LDSM4(r0,r1,r2,r3,addr) \
    asm volatile("ldmatrix.sync.aligned.m8n8.x4.shared.b16 {%0,%1,%2,%3}, [%4];" \
        : "=r"(r0), "=r"(r1), "=r"(r2), "=r"(r3) : "r"(addr))
#define LDSM4T(r0,r1,r2,r3,addr) \
    asm volatile("ldmatrix.sync.aligned.m8n8.x4.trans.shared.b16 {%0,%1,%2,%3}, [%4];" \
        : "=r"(r0), "=r"(r1), "=r"(r2), "=r"(r3) : "r"(addr))
#define CP16(dst, src, sz) \
    asm volatile("cp.async.cg.shared.global [%0], [%1], 16, %2;" \
        :: "r"(dst), "l"(src), "r"(sz) : "memory")
#define CP_COMMIT() asm volatile("cp.async.commit_group;" ::: "memory")
#define CP_WAIT2()  asm volatile("cp.async.wait_group 2;" ::: "memory")

// ---------------- conversion: fp32 -> fp16 ----------------
__global__ void cvt_kernel(const float* __restrict__ src,
                           __half* __restrict__ dst, int n8) {
    int i = blockIdx.x * blockDim.x + threadIdx.x;
    if (i >= n8) return;
    const float4* s = (const float4*)src + 2 * (size_t)i;
    float4 v0 = s[0], v1 = s[1];
    *(uint4*)(dst + 8 * (size_t)i) = make_uint4(
        cvt2h(v0.x, v0.y), cvt2h(v0.z, v0.w), cvt2h(v1.x, v1.y), cvt2h(v1.z, v1.w));
}

// ---------------- routing (proven) ----------------
__global__ void zero_cnt_kernel() { if (threadIdx.x < EXPERTS) g_cnt[threadIdx.x] = 0; }

__global__ void router_logits_kernel(const float* __restrict__ X, const float* __restrict__ Wg) {
    int idx = blockIdx.x * blockDim.x + threadIdx.x;
    int t = idx >> 4, e = idx & 15;
    const float* xr = X + (size_t)t * HIDDEN;
    float s0 = 0.f, s1 = 0.f, s2 = 0.f, s3 = 0.f;
    #pragma unroll 4
    for (int k = 0; k < HIDDEN; k += 4) {
        s0 = fmaf(xr[k+0], Wg[(k+0)*EXPERTS + e], s0);
        s1 = fmaf(xr[k+1], Wg[(k+1)*EXPERTS + e], s1);
        s2 = fmaf(xr[k+2], Wg[(k+2)*EXPERTS + e], s2);
        s3 = fmaf(xr[k+3], Wg[(k+3)*EXPERTS + e], s3);
    }
    g_logits[idx] = (s0 + s1) + (s2 + s3);
}

__global__ void router_topk_kernel() {
    int t = blockIdx.x * blockDim.x + threadIdx.x;
    if (t >= TOKENS) return;
    float l[EXPERTS];
    #pragma unroll
    for (int e = 0; e < EXPERTS; e++) l[e] = g_logits[t * EXPERTS + e];
    int e1 = 0; float v1 = l[0];
    #pragma unroll
    for (int e = 1; e < EXPERTS; e++) if (l[e] > v1) { v1 = l[e]; e1 = e; }
    int e2 = -1; float v2 = -3.4e38f;
    #pragma unroll
    for (int e = 0; e < EXPERTS; e++) { if (e == e1) continue; if (l[e] > v2) { v2 = l[e]; e2 = e; } }
    float w1 = sigmoidf_fast(v1), w2 = sigmoidf_fast(v2);
    float inv = 1.0f / (w1 + w2); w1 *= inv; w2 *= inv;
    int s1 = atomicAdd(&g_cnt[e1], 1);
    int s2 = atomicAdd(&g_cnt[e2], 1);
    g_tok[e1 * TOKENS + s1] = t;
    g_tok[e2 * TOKENS + s2] = t;
    g_te[2*t+0] = e1; g_tslot[2*t+0] = s1; g_tw[2*t+0] = w1;
    g_te[2*t+1] = e2; g_tslot[2*t+1] = s2; g_tw[2*t+1] = w2;
}

__global__ void offsets_kernel() {
    if (threadIdx.x == 0 && blockIdx.x == 0) {
        int a = 0;
        for (int e = 0; e < EXPERTS; e++) { g_off[e] = a; a += g_cnt[e]; }
        g_off[EXPERTS] = a;
    }
}

// ---------------- fp16 single-term mma.sync grouped GEMM ----------------
// CTA tile 128x64, BK=32, 8 warps (2m x 4n), warp tile 64x16, 2 CTAs/SM,
// 4-stage cp.async pipeline with wait_group 2 (2-tile prefetch distance).
// FUSED=1: A = gathered Xh rows; B0=W0h(gate), B1=W1h(up); epi h=silu(g)*u -> g_hh (fp16)
// FUSED=0: A = g_hh rows;        B0=Wdh;                   epi raw -> g_y (fp32)
template <int FUSED>
__global__ __launch_bounds__(256, 2)
void moe_gemm_fp16(const __half* __restrict__ Agh,
                   const __half* __restrict__ B0h_g,
                   const __half* __restrict__ B1h_g,
                   int ebase) {
    constexpr int Kdim = FUSED ? HIDDEN : INTER;
    constexpr int Ndim = FUSED ? INTER : HIDDEN;
    constexpr int KT   = Kdim / 32;
    constexpr int SA   = 40;   // A row stride (halves)
    constexpr int SB   = 72;   // B k-row stride (halves), 64 data + 8 pad
    constexpr int B0H  = 128 * SA;           // 5120 halves
    constexpr int B1H  = B0H + 32 * SB;      // 7424
    constexpr int STAGE_H = B0H + (FUSED ? 2 : 1) * 32 * SB;
    constexpr int STAGE_B = STAGE_H * 2;

    const int e  = ebase + blockIdx.z;
    const int ne = g_cnt[e];
    const int m0 = blockIdx.x * 128;
    if (m0 >= ne) return;
    const int n0  = blockIdx.y * 64;
    const int off = g_off[e];

    extern __shared__ __align__(16) uint16_t smh[];
    const uint32_t sbase = smem_u32(smh);

    const int tid  = threadIdx.x;
    const int lane = tid & 31;
    const int wid  = tid >> 5;
    const int wm   = wid & 1;        // m block 0/64
    const int wn   = wid >> 1;       // n block *16
    const int lg   = lane >> 2;
    const int lt   = lane & 3;
    const int q    = lane >> 3;      // ldmatrix matrix id 0..3
    const int rr   = lane & 7;       // ldmatrix row id

    // A ldmatrix: q0 (m0-7,k0-7), q1 (m8-15,k0-7), q2 (m0-7,k8-15), q3 (m8-15,k8-15)
    const uint32_t a_loff = (uint32_t)(((wm * 64 + (q & 1) * 8 + rr) * SA + (q >> 1) * 8) * 2);
    // B ldmatrix (trans): q0 (k0-7,n0-7), q1 (k8-15,n0-7), q2 (k0-7,n8-15), q3 (k8-15,n8-15)
    const uint32_t b_loff = (uint32_t)((((q & 1) * 8 + rr) * SB + wn * 16 + (q >> 1) * 8) * 2);

    // A cp.async: thread covers row (tid>>1), halves [(tid&1)*16, +16)
    const int ar  = tid >> 1;
    const int ach = (tid & 1) * 16;
    const __half* pAh;
    uint32_t aSz;
    {
        int r = m0 + ar;
        if (FUSED) {
            if (r < ne) {
                pAh = Agh + (size_t)g_tok[e * TOKENS + r] * Kdim + ach; aSz = 16;
            } else { pAh = Agh; aSz = 0; }
        } else {
            pAh = Agh + (size_t)(off + r) * Kdim + ach; aSz = 16;
        }
    }
    const uint32_t dA = (uint32_t)((ar * SA + ach) * 2);
    // B cp.async: thread covers k-row (tid>>3), halves [(tid&7)*8, +8) (16B)
    const int br  = tid >> 3;
    const int bch = (tid & 7) * 8;
    const size_t bstart = (size_t)e * Kdim * Ndim + (size_t)br * Ndim + n0 + bch;
    const __half* pB0h = B0h_g + bstart;
    const __half* pB1h = FUSED ? (B1h_g + bstart) : nullptr;
    const uint32_t dB = (uint32_t)((br * SB + bch) * 2);

    auto issue = [&](int kt, int buf) {
        const uint32_t st = sbase + (uint32_t)buf * STAGE_B;
        const size_t ak = (size_t)kt * 32;
        const size_t bk = (size_t)kt * 32 * Ndim;
        CP16(st + dA,                pAh + ak,     aSz);
        CP16(st + dA + 16,           pAh + ak + 8, aSz);
        CP16(st + dB + B0H * 2,      pB0h + bk,    16u);
        if (FUSED) CP16(st + dB + B1H * 2, pB1h + bk, 16u);
    };

    float accG[4][2][4];
    float accU[FUSED ? 4 : 1][2][4];
    #pragma unroll
    for (int i = 0; i < 4; i++)
        #pragma unroll
        for (int j = 0; j < 2; j++)
            #pragma unroll
            for (int p = 0; p < 4; p++) { accG[i][j][p] = 0.f; if (FUSED) accU[i][j][p] = 0.f; }

    // prologue: issue tiles 0..2 (3 groups), wait until tile 0 resident
    issue(0, 0); CP_COMMIT();
    issue(1, 1); CP_COMMIT();
    issue(2, 2); CP_COMMIT();
    CP_WAIT2();
    __syncthreads();

    for (int kt = 0; kt < KT; kt++) {
        if (kt + 3 < KT) issue(kt + 3, (kt + 3) & 3);
        CP_COMMIT();

        const uint32_t st = sbase + (uint32_t)(kt & 3) * STAGE_B;
        #pragma unroll
        for (int ks = 0; ks < 2; ks++) {
            const uint32_t bks = (uint32_t)(ks * 16 * SB * 2);
            // B fragments: one LDSM4T.x4 per matrix covers k16 x n16
            uint32_t bGh[2][2];
            uint32_t bUh[FUSED ? 2 : 1][2];
            {
                uint32_t t0, t1, t2, t3;
                LDSM4T(t0, t1, t2, t3, st + (uint32_t)(B0H * 2) + b_loff + bks);
                bGh[0][0]=t0; bGh[0][1]=t1; bGh[1][0]=t2; bGh[1][1]=t3;
                if (FUSED) {
                    LDSM4T(t0, t1, t2, t3, st + (uint32_t)(B1H * 2) + b_loff + bks);
                    bUh[0][0]=t0; bUh[0][1]=t1; bUh[1][0]=t2; bUh[1][1]=t3;
                }
            }
            #pragma unroll
            for (int mf = 0; mf < 4; mf++) {
                uint32_t ah[4];
                const uint32_t aa = st + a_loff + (uint32_t)(mf * 16 * SA * 2) + (uint32_t)(ks * 32);
                LDSM4(ah[0], ah[1], ah[2], ah[3], aa);
                #pragma unroll
                for (int nf = 0; nf < 2; nf++) {
                    mma16(accG[mf][nf], ah, bGh[nf]);
                    if (FUSED) mma16(accU[mf][nf], ah, bUh[nf]);
                }
            }
        }
        CP_WAIT2();
        __syncthreads();
    }

    // ---- epilogue ----
    #pragma unroll
    for (int mf = 0; mf < 4; mf++) {
        #pragma unroll
        for (int h = 0; h < 2; h++) {
            int r = m0 + wm * 64 + mf * 16 + lg + h * 8;
            if (r >= ne) continue;
            int col = n0 + wn * 16 + lt * 2;
            if (FUSED) {
                size_t base = (size_t)(off + r) * INTER + col;
                #pragma unroll
                for (int nf = 0; nf < 2; nf++) {
                    float g0 = accG[mf][nf][2*h],   g1 = accG[mf][nf][2*h+1];
                    float u0 = accU[mf][nf][2*h],   u1 = accU[mf][nf][2*h+1];
                    float h0 = g0 * sigmoidf_fast(g0) * u0;
                    float h1 = g1 * sigmoidf_fast(g1) * u1;
                    *(uint32_t*)(g_hh + base + nf * 8) = cvt2h(h0, h1);
                }
            } else {
                float* orow = g_y + (size_t)(off + r) * HIDDEN + col;
                #pragma unroll
                for (int nf = 0; nf < 2; nf++) {
                    float2 v = make_float2(accG[mf][nf][2*h], accG[mf][nf][2*h+1]);
                    *(float2*)(orow + nf * 8) = v;
                }
            }
        }
    }
}

// ---------------- combine ----------------
__global__ void combine_kernel(float* __restrict__ out) {
    int idx = blockIdx.x * blockDim.x + threadIdx.x;
    int t = idx / (HIDDEN / 4);
    int c = idx % (HIDDEN / 4);
    int e0 = g_te[2*t], e1 = g_te[2*t+1];
    size_t p0 = (size_t)g_off[e0] + g_tslot[2*t];
    size_t p1 = (size_t)g_off[e1] + g_tslot[2*t+1];
    float w0 = g_tw[2*t], w1 = g_tw[2*t+1];
    float4 y0 = *(const float4*)(g_y + p0 * HIDDEN + 4*c);
    float4 y1 = *(const float4*)(g_y + p1 * HIDDEN + 4*c);
    float4 r;
    r.x = w0*y0.x + w1*y1.x; r.y = w0*y0.y + w1*y1.y;
    r.z = w0*y0.z + w1*y1.z; r.w = w0*y0.w + w1*y1.w;
    *(float4*)(out + (size_t)t * HIDDEN + 4*c) = r;
}

// ---------------- launcher (R9-proven schedule) ----------------
extern "C" void kernel_launch(void* const* d_in, const int* in_sizes, int n_in,
                              void* d_out, int out_size) {
    const float* X   = (const float*)d_in[0];
    const float* Wg  = (const float*)d_in[1];
    const float* Wgp = (const float*)d_in[2];
    const float* Wup = (const float*)d_in[3];
    const float* Wdp = (const float*)d_in[4];
    float* out = (float*)d_out;

    __half *xh, *w0h, *w1h, *wdh, *hh;
    cudaGetSymbolAddress((void**)&xh,  c_Xh);
    cudaGetSymbolAddress((void**)&w0h, c_W0h);
    cudaGetSymbolAddress((void**)&w1h, c_W1h);
    cudaGetSymbolAddress((void**)&wdh, c_Wdh);
    cudaGetSymbolAddress((void**)&hh,  g_hh);

    constexpr int STAGE_F = (128*40 + 2*32*72) * 2;   // 19456 B
    constexpr int STAGE_D = (128*40 + 1*32*72) * 2;   // 14848 B
    const int SMEM_F = 4 * STAGE_F;                   // 77824
    const int SMEM_D = 4 * STAGE_D;                   // 59392
    cudaFuncSetAttribute(moe_gemm_fp16<1>, cudaFuncAttributeMaxDynamicSharedMemorySize, SMEM_F);
    cudaFuncSetAttribute(moe_gemm_fp16<0>, cudaFuncAttributeMaxDynamicSharedMemorySize, SMEM_D);

    // ONE aux stream + 3 events (R9-proven footprint)
    static cudaStream_t sAux = nullptr;
    static cudaEvent_t  evFork = nullptr, evX = nullptr, evWd = nullptr;
    if (sAux == nullptr) {
        cudaStreamCreateWithFlags(&sAux, cudaStreamNonBlocking);
        cudaEventCreateWithFlags(&evFork, cudaEventDisableTiming);
        cudaEventCreateWithFlags(&evX,    cudaEventDisableTiming);
        cudaEventCreateWithFlags(&evWd,   cudaEventDisableTiming);
    }

    const int NX = TOKENS * HIDDEN / 8;
    const int NW = EXPERTS * HIDDEN * INTER / 8;

    // ---- fork aux off the main (capture) stream ----
    cudaEventRecord(evFork, 0);
    cudaStreamWaitEvent(sAux, evFork, 0);

    // aux: routing + X conversion, then Wd conversion (overlaps fused GEMM)
    zero_cnt_kernel<<<1, 32, 0, sAux>>>();
    router_logits_kernel<<<(TOKENS * EXPERTS) / 256, 256, 0, sAux>>>(X, Wg);
    router_topk_kernel<<<(TOKENS + 255) / 256, 256, 0, sAux>>>();
    offsets_kernel<<<1, 1, 0, sAux>>>();
    cvt_kernel<<<(NX + 255) / 256, 256, 0, sAux>>>(X, xh, NX);
    cudaEventRecord(evX, sAux);
    cvt_kernel<<<(NW + 255) / 256, 256, 0, sAux>>>(Wdp, wdh, NW);
    cudaEventRecord(evWd, sAux);

    // main: gate/up weight conversion
    cvt_kernel<<<(NW + 255) / 256, 256>>>(Wgp, w0h, NW);
    cvt_kernel<<<(NW + 255) / 256, 256>>>(Wup, w1h, NW);

    // join: fused GEMM needs router + xh (+ w0h/w1h via stream order)
    cudaStreamWaitEvent(0, evX, 0);
    dim3 grid_f(TOKENS / 128, INTER / 64, EXPERTS);    // (16, 22, 16)
    moe_gemm_fp16<1><<<grid_f, 256, SMEM_F>>>(xh, w0h, w1h, 0);

    // join: down GEMM additionally needs wdh
    cudaStreamWaitEvent(0, evWd, 0);
    dim3 grid_d(TOKENS / 128, HIDDEN / 64, EXPERTS);   // (16, 32, 16)
    moe_gemm_fp16<0><<<grid_d, 256, SMEM_D>>>(hh, wdh, nullptr, 0);

    combine_kernel<<<(TOKENS * (HIDDEN / 4)) / 256, 256>>>(out);
}

// round 15
// speedup vs baseline: 1.2664x; 1.0183x over previous
#include <cuda_runtime.h>
#include <cuda_fp16.h>
#include <cstdint>
#include <math.h>

#define TOKENS  2048
#define HIDDEN  2048
#define INTER   1408
#define EXPERTS 16
#define MAXPAIRS (TOKENS*2)

// ---------------- scratch ----------------
__device__ int   g_cnt[EXPERTS];
__device__ int   g_off[EXPERTS + 1];
__device__ int   g_tok[EXPERTS * TOKENS];
__device__ int   g_te[MAXPAIRS];
__device__ int   g_tslot[MAXPAIRS];
__device__ float g_tw[MAXPAIRS];
__device__ float g_logits[TOKENS * EXPERTS];
__device__ float g_y[(size_t)MAXPAIRS * HIDDEN];

// fp16 operands (single-term)
__device__ __half c_Xh[(size_t)TOKENS * HIDDEN];
__device__ __half c_W0h[(size_t)EXPERTS * HIDDEN * INTER];
__device__ __half c_W1h[(size_t)EXPERTS * HIDDEN * INTER];
__device__ __half c_Wdh[(size_t)EXPERTS * INTER * HIDDEN];
__device__ __half g_hh[(size_t)(MAXPAIRS + 128) * INTER];

// ---------------- helpers ----------------
__device__ __forceinline__ float sigmoidf_fast(float x) { return 1.0f / (1.0f + __expf(-x)); }

__device__ __forceinline__ uint32_t smem_u32(const void* p) {
    uint32_t a;
    asm("{ .reg .u64 t; cvta.to.shared.u64 t, %1; cvt.u32.u64 %0, t; }" : "=r"(a) : "l"(p));
    return a;
}
__device__ __forceinline__ uint32_t cvt2h(float x, float y) {
    __half2 h = __floats2half2_rn(x, y);
    return *(uint32_t*)&h;
}
// m16n8k16 fp16 MMA, fp32 accum
__device__ __forceinline__ void mma16(float* d, const uint32_t* a, const uint32_t* b) {
    asm volatile("mma.sync.aligned.m16n8k16.row.col.f32.f16.f16.f32 "
        "{%0,%1,%2,%3}, {%4,%5,%6,%7}, {%8,%9}, {%0,%1,%2,%3};"
        : "+f"(d[0]), "+f"(d[1]), "+f"(d[2]), "+f"(d[3])
        : "r"(a[0]), "r"(a[1]), "r"(a[2]), "r"(a[3]), "r"(b[0]), "r"(b[1]));
}
#define LDSM4(r0,r1,r2,r3,addr) \
    asm volatile("ldmatrix.sync.aligned.m8n8.x4.shared.b16 {%0,%1,%2,%3}, [%4];" \
        : "=r"(r0), "=r"(r1), "=r"(r2), "=r"(r3) : "r"(addr))
#define LDSM4T(r0,r1,r2,r3,addr) \
    asm volatile("ldmatrix.sync.aligned.m8n8.x4.trans.shared.b16 {%0,%1,%2,%3}, [%4];" \
        : "=r"(r0), "=r"(r1), "=r"(r2), "=r"(r3) : "r"(addr))
#define CP16(dst, src, sz) \
    asm volatile("cp.async.cg.shared.global [%0], [%1], 16, %2;" \
        :: "r"(dst), "l"(src), "r"(sz) : "memory")
#define CP_COMMIT() asm volatile("cp.async.commit_group;" ::: "memory")
#define CP_WAIT3()  asm volatile("cp.async.wait_group 3;" ::: "memory")

// ---------------- conversion: fp32 -> fp16 ----------------
__global__ void cvt_kernel(const float* __restrict__ src,
                           __half* __restrict__ dst, int n8) {
    int i = blockIdx.x * blockDim.x + threadIdx.x;
    if (i >= n8) return;
    const float4* s = (const float4*)src + 2 * (size_t)i;
    float4 v0 = s[0], v1 = s[1];
    *(uint4*)(dst + 8 * (size_t)i) = make_uint4(
        cvt2h(v0.x, v0.y), cvt2h(v0.z, v0.w), cvt2h(v1.x, v1.y), cvt2h(v1.z, v1.w));
}

// ---------------- routing (proven) ----------------
__global__ void zero_cnt_kernel() { if (threadIdx.x < EXPERTS) g_cnt[threadIdx.x] = 0; }

__global__ void router_logits_kernel(const float* __restrict__ X, const float* __restrict__ Wg) {
    int idx = blockIdx.x * blockDim.x + threadIdx.x;
    int t = idx >> 4, e = idx & 15;
    const float* xr = X + (size_t)t * HIDDEN;
    float s0 = 0.f, s1 = 0.f, s2 = 0.f, s3 = 0.f;
    #pragma unroll 4
    for (int k = 0; k < HIDDEN; k += 4) {
        s0 = fmaf(xr[k+0], Wg[(k+0)*EXPERTS + e], s0);
        s1 = fmaf(xr[k+1], Wg[(k+1)*EXPERTS + e], s1);
        s2 = fmaf(xr[k+2], Wg[(k+2)*EXPERTS + e], s2);
        s3 = fmaf(xr[k+3], Wg[(k+3)*EXPERTS + e], s3);
    }
    g_logits[idx] = (s0 + s1) + (s2 + s3);
}

__global__ void router_topk_kernel() {
    int t = blockIdx.x * blockDim.x + threadIdx.x;
    if (t >= TOKENS) return;
    float l[EXPERTS];
    #pragma unroll
    for (int e = 0; e < EXPERTS; e++) l[e] = g_logits[t * EXPERTS + e];
    int e1 = 0; float v1 = l[0];
    #pragma unroll
    for (int e = 1; e < EXPERTS; e++) if (l[e] > v1) { v1 = l[e]; e1 = e; }
    int e2 = -1; float v2 = -3.4e38f;
    #pragma unroll
    for (int e = 0; e < EXPERTS; e++) { if (e == e1) continue; if (l[e] > v2) { v2 = l[e]; e2 = e; } }
    float w1 = sigmoidf_fast(v1), w2 = sigmoidf_fast(v2);
    float inv = 1.0f / (w1 + w2); w1 *= inv; w2 *= inv;
    int s1 = atomicAdd(&g_cnt[e1], 1);
    int s2 = atomicAdd(&g_cnt[e2], 1);
    g_tok[e1 * TOKENS + s1] = t;
    g_tok[e2 * TOKENS + s2] = t;
    g_te[2*t+0] = e1; g_tslot[2*t+0] = s1; g_tw[2*t+0] = w1;
    g_te[2*t+1] = e2; g_tslot[2*t+1] = s2; g_tw[2*t+1] = w2;
}

__global__ void offsets_kernel() {
    if (threadIdx.x == 0 && blockIdx.x == 0) {
        int a = 0;
        for (int e = 0; e < EXPERTS; e++) { g_off[e] = a; a += g_cnt[e]; }
        g_off[EXPERTS] = a;
    }
}

// ---------------- fp16 single-term mma.sync grouped GEMM ----------------
// CTA tile 128x64, BK=32, 8 warps (2m x 4n), warp tile 64x16, 2 CTAs/SM,
// 5-stage cp.async pipeline with wait_group 3 (3-tile prefetch distance).
// FUSED=1: A = gathered Xh rows; B0=W0h(gate), B1=W1h(up); epi h=silu(g)*u -> g_hh (fp16)
// FUSED=0: A = g_hh rows;        B0=Wdh;                   epi raw -> g_y (fp32)
template <int FUSED>
__global__ __launch_bounds__(256, 2)
void moe_gemm_fp16(const __half* __restrict__ Agh,
                   const __half* __restrict__ B0h_g,
                   const __half* __restrict__ B1h_g,
                   int ebase) {
    constexpr int Kdim = FUSED ? HIDDEN : INTER;
    constexpr int Ndim = FUSED ? INTER : HIDDEN;
    constexpr int KT   = Kdim / 32;
    constexpr int SA   = 40;   // A row stride (halves)
    constexpr int SB   = 72;   // B k-row stride (halves), 64 data + 8 pad
    constexpr int B0H  = 128 * SA;           // 5120 halves
    constexpr int B1H  = B0H + 32 * SB;      // 7424
    constexpr int STAGE_H = B0H + (FUSED ? 2 : 1) * 32 * SB;
    constexpr int STAGE_B = STAGE_H * 2;

    const int e  = ebase + blockIdx.z;
    const int ne = g_cnt[e];
    const int m0 = blockIdx.x * 128;
    if (m0 >= ne) return;
    const int n0  = blockIdx.y * 64;
    const int off = g_off[e];

    extern __shared__ __align__(16) uint16_t smh[];
    const uint32_t sbase = smem_u32(smh);

    const int tid  = threadIdx.x;
    const int lane = tid & 31;
    const int wid  = tid >> 5;
    const int wm   = wid & 1;        // m block 0/64
    const int wn   = wid >> 1;       // n block *16
    const int lg   = lane >> 2;
    const int lt   = lane & 3;
    const int q    = lane >> 3;      // ldmatrix matrix id 0..3
    const int rr   = lane & 7;       // ldmatrix row id

    const uint32_t a_loff = (uint32_t)(((wm * 64 + (q & 1) * 8 + rr) * SA + (q >> 1) * 8) * 2);
    const uint32_t b_loff = (uint32_t)((((q & 1) * 8 + rr) * SB + wn * 16 + (q >> 1) * 8) * 2);

    // A cp.async: thread covers row (tid>>1), halves [(tid&1)*16, +16)
    const int ar  = tid >> 1;
    const int ach = (tid & 1) * 16;
    const __half* pAh;
    uint32_t aSz;
    {
        int r = m0 + ar;
        if (FUSED) {
            if (r < ne) {
                pAh = Agh + (size_t)g_tok[e * TOKENS + r] * Kdim + ach; aSz = 16;
            } else { pAh = Agh; aSz = 0; }
        } else {
            pAh = Agh + (size_t)(off + r) * Kdim + ach; aSz = 16;
        }
    }
    const uint32_t dA = (uint32_t)((ar * SA + ach) * 2);
    // B cp.async: thread covers k-row (tid>>3), halves [(tid&7)*8, +8) (16B)
    const int br  = tid >> 3;
    const int bch = (tid & 7) * 8;
    const size_t bstart = (size_t)e * Kdim * Ndim + (size_t)br * Ndim + n0 + bch;
    const __half* pB0h = B0h_g + bstart;
    const __half* pB1h = FUSED ? (B1h_g + bstart) : nullptr;
    const uint32_t dB = (uint32_t)((br * SB + bch) * 2);

    auto issue = [&](int kt, int buf) {
        const uint32_t st = sbase + (uint32_t)buf * STAGE_B;
        const size_t ak = (size_t)kt * 32;
        const size_t bk = (size_t)kt * 32 * Ndim;
        CP16(st + dA,                pAh + ak,     aSz);
        CP16(st + dA + 16,           pAh + ak + 8, aSz);
        CP16(st + dB + B0H * 2,      pB0h + bk,    16u);
        if (FUSED) CP16(st + dB + B1H * 2, pB1h + bk, 16u);
    };

    float accG[4][2][4];
    float accU[FUSED ? 4 : 1][2][4];
    #pragma unroll
    for (int i = 0; i < 4; i++)
        #pragma unroll
        for (int j = 0; j < 2; j++)
            #pragma unroll
            for (int p = 0; p < 4; p++) { accG[i][j][p] = 0.f; if (FUSED) accU[i][j][p] = 0.f; }

    // prologue: issue tiles 0..3 (4 groups), wait until tile 0 resident
    issue(0, 0); CP_COMMIT();
    issue(1, 1); CP_COMMIT();
    issue(2, 2); CP_COMMIT();
    issue(3, 3); CP_COMMIT();
    CP_WAIT3();
    __syncthreads();

    int buf = 0, pbuf = 4;   // compute buffer, prefetch buffer (kt+4)%5
    for (int kt = 0; kt < KT; kt++) {
        if (kt + 4 < KT) issue(kt + 4, pbuf);
        CP_COMMIT();

        const uint32_t st = sbase + (uint32_t)buf * STAGE_B;
        #pragma unroll
        for (int ks = 0; ks < 2; ks++) {
            const uint32_t bks = (uint32_t)(ks * 16 * SB * 2);
            uint32_t bGh[2][2];
            uint32_t bUh[FUSED ? 2 : 1][2];
            {
                uint32_t t0, t1, t2, t3;
                LDSM4T(t0, t1, t2, t3, st + (uint32_t)(B0H * 2) + b_loff + bks);
                bGh[0][0]=t0; bGh[0][1]=t1; bGh[1][0]=t2; bGh[1][1]=t3;
                if (FUSED) {
                    LDSM4T(t0, t1, t2, t3, st + (uint32_t)(B1H * 2) + b_loff + bks);
                    bUh[0][0]=t0; bUh[0][1]=t1; bUh[1][0]=t2; bUh[1][1]=t3;
                }
            }
            #pragma unroll
            for (int mf = 0; mf < 4; mf++) {
                uint32_t ah[4];
                const uint32_t aa = st + a_loff + (uint32_t)(mf * 16 * SA * 2) + (uint32_t)(ks * 32);
                LDSM4(ah[0], ah[1], ah[2], ah[3], aa);
                #pragma unroll
                for (int nf = 0; nf < 2; nf++) {
                    mma16(accG[mf][nf], ah, bGh[nf]);
                    if (FUSED) mma16(accU[mf][nf], ah, bUh[nf]);
                }
            }
        }
        CP_WAIT3();
        __syncthreads();
        buf  = (buf  == 4) ? 0 : buf + 1;
        pbuf = (pbuf == 4) ? 0 : pbuf + 1;
    }

    // ---- epilogue ----
    #pragma unroll
    for (int mf = 0; mf < 4; mf++) {
        #pragma unroll
        for (int h = 0; h < 2; h++) {
            int r = m0 + wm * 64 + mf * 16 + lg + h * 8;
            if (r >= ne) continue;
            int col = n0 + wn * 16 + lt * 2;
            if (FUSED) {
                size_t base = (size_t)(off + r) * INTER + col;
                #pragma unroll
                for (int nf = 0; nf < 2; nf++) {
                    float g0 = accG[mf][nf][2*h],   g1 = accG[mf][nf][2*h+1];
                    float u0 = accU[mf][nf][2*h],   u1 = accU[mf][nf][2*h+1];
                    float h0 = g0 * sigmoidf_fast(g0) * u0;
                    float h1 = g1 * sigmoidf_fast(g1) * u1;
                    *(uint32_t*)(g_hh + base + nf * 8) = cvt2h(h0, h1);
                }
            } else {
                float* orow = g_y + (size_t)(off + r) * HIDDEN + col;
                #pragma unroll
                for (int nf = 0; nf < 2; nf++) {
                    float2 v = make_float2(accG[mf][nf][2*h], accG[mf][nf][2*h+1]);
                    *(float2*)(orow + nf * 8) = v;
                }
            }
        }
    }
}

// ---------------- combine ----------------
__global__ void combine_kernel(float* __restrict__ out) {
    int idx = blockIdx.x * blockDim.x + threadIdx.x;
    int t = idx / (HIDDEN / 4);
    int c = idx % (HIDDEN / 4);
    int e0 = g_te[2*t], e1 = g_te[2*t+1];
    size_t p0 = (size_t)g_off[e0] + g_tslot[2*t];
    size_t p1 = (size_t)g_off[e1] + g_tslot[2*t+1];
    float w0 = g_tw[2*t], w1 = g_tw[2*t+1];
    float4 y0 = *(const float4*)(g_y + p0 * HIDDEN + 4*c);
    float4 y1 = *(const float4*)(g_y + p1 * HIDDEN + 4*c);
    float4 r;
    r.x = w0*y0.x + w1*y1.x; r.y = w0*y0.y + w1*y1.y;
    r.z = w0*y0.z + w1*y1.z; r.w = w0*y0.w + w1*y1.w;
    *(float4*)(out + (size_t)t * HIDDEN + 4*c) = r;
}

// ---------------- launcher ----------------
extern "C" void kernel_launch(void* const* d_in, const int* in_sizes, int n_in,
                              void* d_out, int out_size) {
    const float* X   = (const float*)d_in[0];
    const float* Wg  = (const float*)d_in[1];
    const float* Wgp = (const float*)d_in[2];
    const float* Wup = (const float*)d_in[3];
    const float* Wdp = (const float*)d_in[4];
    float* out = (float*)d_out;

    __half *xh, *w0h, *w1h, *wdh, *hh;
    cudaGetSymbolAddress((void**)&xh,  c_Xh);
    cudaGetSymbolAddress((void**)&w0h, c_W0h);
    cudaGetSymbolAddress((void**)&w1h, c_W1h);
    cudaGetSymbolAddress((void**)&wdh, c_Wdh);
    cudaGetSymbolAddress((void**)&hh,  g_hh);

    constexpr int STAGE_F = (128*40 + 2*32*72) * 2;   // 19456 B
    constexpr int STAGE_D = (128*40 + 1*32*72) * 2;   // 14848 B
    const int SMEM_F = 5 * STAGE_F;                   // 97280
    const int SMEM_D = 5 * STAGE_D;                   // 74240
    cudaFuncSetAttribute(moe_gemm_fp16<1>, cudaFuncAttributeMaxDynamicSharedMemorySize, SMEM_F);
    cudaFuncSetAttribute(moe_gemm_fp16<0>, cudaFuncAttributeMaxDynamicSharedMemorySize, SMEM_D);

    // ONE aux stream + 4 events (proven-safe footprint)
    static cudaStream_t sAux = nullptr;
    static cudaEvent_t  evFork = nullptr, evX = nullptr, evWm = nullptr, evWd = nullptr;
    if (sAux == nullptr) {
        cudaStreamCreateWithFlags(&sAux, cudaStreamNonBlocking);
        cudaEventCreateWithFlags(&evFork, cudaEventDisableTiming);
        cudaEventCreateWithFlags(&evX,    cudaEventDisableTiming);
        cudaEventCreateWithFlags(&evWm,   cudaEventDisableTiming);
        cudaEventCreateWithFlags(&evWd,   cudaEventDisableTiming);
    }

    const int NX = TOKENS * HIDDEN / 8;
    const int NW = EXPERTS * HIDDEN * INTER / 8;

    // ---- fork aux off the main (capture) stream ----
    cudaEventRecord(evFork, 0);
    cudaStreamWaitEvent(sAux, evFork, 0);

    // aux: routing + X conversion (light traffic); Wd cvt DEFERRED until main's
    // W0/W1 cvt finishes, so it runs under the fused GEMM instead of stealing
    // head bandwidth.
    zero_cnt_kernel<<<1, 32, 0, sAux>>>();
    router_logits_kernel<<<(TOKENS * EXPERTS) / 256, 256, 0, sAux>>>(X, Wg);
    router_topk_kernel<<<(TOKENS + 255) / 256, 256, 0, sAux>>>();
    offsets_kernel<<<1, 1, 0, sAux>>>();
    cvt_kernel<<<(NX + 255) / 256, 256, 0, sAux>>>(X, xh, NX);
    cudaEventRecord(evX, sAux);

    // main: gate/up weight conversion at full bandwidth
    cvt_kernel<<<(NW + 255) / 256, 256>>>(Wgp, w0h, NW);
    cvt_kernel<<<(NW + 255) / 256, 256>>>(Wup, w1h, NW);
    cudaEventRecord(evWm, 0);

    // aux: Wd conversion overlapped with fused GEMM
    cudaStreamWaitEvent(sAux, evWm, 0);
    cvt_kernel<<<(NW + 255) / 256, 256, 0, sAux>>>(Wdp, wdh, NW);
    cudaEventRecord(evWd, sAux);

    // main: fused GEMM (needs router + xh via evX; w0h/w1h via stream order)
    cudaStreamWaitEvent(0, evX, 0);
    dim3 grid_f(TOKENS / 128, INTER / 64, EXPERTS);    // (16, 22, 16)
    moe_gemm_fp16<1><<<grid_f, 256, SMEM_F>>>(xh, w0h, w1h, 0);

    // main: down GEMM (needs g_hh via stream order + wdh via event)
    cudaStreamWaitEvent(0, evWd, 0);
    dim3 grid_d(TOKENS / 128, HIDDEN / 64, EXPERTS);   // (16, 32, 16)
    moe_gemm_fp16<0><<<grid_d, 256, SMEM_D>>>(hh, wdh, nullptr, 0);

    combine_kernel<<<(TOKENS * (HIDDEN / 4)) / 256, 256>>>(out);
}

// round 16
// speedup vs baseline: 1.2682x; 1.0014x over previous
#include <cuda_runtime.h>
#include <cuda_fp16.h>
#include <cstdint>
#include <math.h>

#define TOKENS  2048
#define HIDDEN  2048
#define INTER   1408
#define EXPERTS 16
#define MAXPAIRS (TOKENS*2)

// ---------------- scratch ----------------
__device__ int   g_cnt[EXPERTS];
__device__ int   g_off[EXPERTS + 1];
__device__ int   g_tok[EXPERTS * TOKENS];
__device__ float g_wslot[EXPERTS * TOKENS];   // routing weight per (expert, slot)
__device__ float g_logits[TOKENS * EXPERTS];

// fp16 operands (single-term)
__device__ __half c_Xh[(size_t)TOKENS * HIDDEN];
__device__ __half c_W0h[(size_t)EXPERTS * HIDDEN * INTER];
__device__ __half c_W1h[(size_t)EXPERTS * HIDDEN * INTER];
__device__ __half c_Wdh[(size_t)EXPERTS * INTER * HIDDEN];
__device__ __half g_hh[(size_t)(MAXPAIRS + 128) * INTER];

// ---------------- helpers ----------------
__device__ __forceinline__ float sigmoidf_fast(float x) { return 1.0f / (1.0f + __expf(-x)); }

__device__ __forceinline__ uint32_t smem_u32(const void* p) {
    uint32_t a;
    asm("{ .reg .u64 t; cvta.to.shared.u64 t, %1; cvt.u32.u64 %0, t; }" : "=r"(a) : "l"(p));
    return a;
}
__device__ __forceinline__ uint32_t cvt2h(float x, float y) {
    __half2 h = __floats2half2_rn(x, y);
    return *(uint32_t*)&h;
}
// m16n8k16 fp16 MMA, fp32 accum
__device__ __forceinline__ void mma16(float* d, const uint32_t* a, const uint32_t* b) {
    asm volatile("mma.sync.aligned.m16n8k16.row.col.f32.f16.f16.f32 "
        "{%0,%1,%2,%3}, {%4,%5,%6,%7}, {%8,%9}, {%0,%1,%2,%3};"
        : "+f"(d[0]), "+f"(d[1]), "+f"(d[2]), "+f"(d[3])
        : "r"(a[0]), "r"(a[1]), "r"(a[2]), "r"(a[3]), "r"(b[0]), "r"(b[1]));
}
#define LDSM4(r0,r1,r2,r3,addr) \
    asm volatile("ldmatrix.sync.aligned.m8n8.x4.shared.b16 {%0,%1,%2,%3}, [%4];" \
        : "=r"(r0), "=r"(r1), "=r"(r2), "=r"(r3) : "r"(addr))
#define LDSM4T(r0,r1,r2,r3,addr) \
    asm volatile("ldmatrix.sync.aligned.m8n8.x4.trans.shared.b16 {%0,%1,%2,%3}, [%4];" \
        : "=r"(r0), "=r"(r1), "=r"(r2), "=r"(r3) : "r"(addr))
#define CP16(dst, src, sz) \
    asm volatile("cp.async.cg.shared.global [%0], [%1], 16, %2;" \
        :: "r"(dst), "l"(src), "r"(sz) : "memory")
#define CP_COMMIT() asm volatile("cp.async.commit_group;" ::: "memory")
#define CP_WAIT3()  asm volatile("cp.async.wait_group 3;" ::: "memory")

// ---------------- conversion: fp32 -> fp16 ----------------
__global__ void cvt_kernel(const float* __restrict__ src,
                           __half* __restrict__ dst, int n8) {
    int i = blockIdx.x * blockDim.x + threadIdx.x;
    if (i >= n8) return;
    const float4* s = (const float4*)src + 2 * (size_t)i;
    float4 v0 = s[0], v1 = s[1];
    *(uint4*)(dst + 8 * (size_t)i) = make_uint4(
        cvt2h(v0.x, v0.y), cvt2h(v0.z, v0.w), cvt2h(v1.x, v1.y), cvt2h(v1.z, v1.w));
}

// ---------------- zero the output (poisoned by harness) ----------------
__global__ void zero_out_kernel(float* __restrict__ out) {
    int i = blockIdx.x * blockDim.x + threadIdx.x;   // TOKENS*HIDDEN/4 threads
    *(float4*)(out + 4 * (size_t)i) = make_float4(0.f, 0.f, 0.f, 0.f);
}

// ---------------- routing (proven) ----------------
__global__ void zero_cnt_kernel() { if (threadIdx.x < EXPERTS) g_cnt[threadIdx.x] = 0; }

__global__ void router_logits_kernel(const float* __restrict__ X, const float* __restrict__ Wg) {
    int idx = blockIdx.x * blockDim.x + threadIdx.x;
    int t = idx >> 4, e = idx & 15;
    const float* xr = X + (size_t)t * HIDDEN;
    float s0 = 0.f, s1 = 0.f, s2 = 0.f, s3 = 0.f;
    #pragma unroll 4
    for (int k = 0; k < HIDDEN; k += 4) {
        s0 = fmaf(xr[k+0], Wg[(k+0)*EXPERTS + e], s0);
        s1 = fmaf(xr[k+1], Wg[(k+1)*EXPERTS + e], s1);
        s2 = fmaf(xr[k+2], Wg[(k+2)*EXPERTS + e], s2);
        s3 = fmaf(xr[k+3], Wg[(k+3)*EXPERTS + e], s3);
    }
    g_logits[idx] = (s0 + s1) + (s2 + s3);
}

__global__ void router_topk_kernel() {
    int t = blockIdx.x * blockDim.x + threadIdx.x;
    if (t >= TOKENS) return;
    float l[EXPERTS];
    #pragma unroll
    for (int e = 0; e < EXPERTS; e++) l[e] = g_logits[t * EXPERTS + e];
    int e1 = 0; float v1 = l[0];
    #pragma unroll
    for (int e = 1; e < EXPERTS; e++) if (l[e] > v1) { v1 = l[e]; e1 = e; }
    int e2 = -1; float v2 = -3.4e38f;
    #pragma unroll
    for (int e = 0; e < EXPERTS; e++) { if (e == e1) continue; if (l[e] > v2) { v2 = l[e]; e2 = e; } }
    float w1 = sigmoidf_fast(v1), w2 = sigmoidf_fast(v2);
    float inv = 1.0f / (w1 + w2); w1 *= inv; w2 *= inv;
    int s1 = atomicAdd(&g_cnt[e1], 1);
    int s2 = atomicAdd(&g_cnt[e2], 1);
    g_tok[e1 * TOKENS + s1] = t;   g_wslot[e1 * TOKENS + s1] = w1;
    g_tok[e2 * TOKENS + s2] = t;   g_wslot[e2 * TOKENS + s2] = w2;
}

__global__ void offsets_kernel() {
    if (threadIdx.x == 0 && blockIdx.x == 0) {
        int a = 0;
        for (int e = 0; e < EXPERTS; e++) { g_off[e] = a; a += g_cnt[e]; }
        g_off[EXPERTS] = a;
    }
}

// ---------------- fp16 single-term mma.sync grouped GEMM ----------------
// CTA tile 128x64, BK=32, 8 warps (2m x 4n), warp tile 64x16, 2 CTAs/SM,
// 5-stage cp.async pipeline with wait_group 3.
// FUSED=1: A = gathered Xh rows; B0=W0h(gate), B1=W1h(up); epi h=silu(g)*u -> g_hh (fp16)
// FUSED=0: A = g_hh rows;        B0=Wdh; epi atomicAdd(out[token], w * v)  (fused combine)
template <int FUSED>
__global__ __launch_bounds__(256, 2)
void moe_gemm_fp16(const __half* __restrict__ Agh,
                   const __half* __restrict__ B0h_g,
                   const __half* __restrict__ B1h_g,
                   float* __restrict__ outp,
                   int ebase) {
    constexpr int Kdim = FUSED ? HIDDEN : INTER;
    constexpr int Ndim = FUSED ? INTER : HIDDEN;
    constexpr int KT   = Kdim / 32;
    constexpr int SA   = 40;   // A row stride (halves)
    constexpr int SB   = 72;   // B k-row stride (halves), 64 data + 8 pad
    constexpr int B0H  = 128 * SA;           // 5120 halves
    constexpr int B1H  = B0H + 32 * SB;      // 7424
    constexpr int STAGE_H = B0H + (FUSED ? 2 : 1) * 32 * SB;
    constexpr int STAGE_B = STAGE_H * 2;

    const int e  = ebase + blockIdx.z;
    const int ne = g_cnt[e];
    const int m0 = blockIdx.x * 128;
    if (m0 >= ne) return;
    const int n0  = blockIdx.y * 64;
    const int off = g_off[e];

    extern __shared__ __align__(16) uint16_t smh[];
    const uint32_t sbase = smem_u32(smh);

    const int tid  = threadIdx.x;
    const int lane = tid & 31;
    const int wid  = tid >> 5;
    const int wm   = wid & 1;        // m block 0/64
    const int wn   = wid >> 1;       // n block *16
    const int lg   = lane >> 2;
    const int lt   = lane & 3;
    const int q    = lane >> 3;      // ldmatrix matrix id 0..3
    const int rr   = lane & 7;       // ldmatrix row id

    const uint32_t a_loff = (uint32_t)(((wm * 64 + (q & 1) * 8 + rr) * SA + (q >> 1) * 8) * 2);
    const uint32_t b_loff = (uint32_t)((((q & 1) * 8 + rr) * SB + wn * 16 + (q >> 1) * 8) * 2);

    // A cp.async: thread covers row (tid>>1), halves [(tid&1)*16, +16)
    const int ar  = tid >> 1;
    const int ach = (tid & 1) * 16;
    const __half* pAh;
    uint32_t aSz;
    {
        int r = m0 + ar;
        if (FUSED) {
            if (r < ne) {
                pAh = Agh + (size_t)g_tok[e * TOKENS + r] * Kdim + ach; aSz = 16;
            } else { pAh = Agh; aSz = 0; }
        } else {
            pAh = Agh + (size_t)(off + r) * Kdim + ach; aSz = 16;
        }
    }
    const uint32_t dA = (uint32_t)((ar * SA + ach) * 2);
    // B cp.async: thread covers k-row (tid>>3), halves [(tid&7)*8, +8) (16B)
    const int br  = tid >> 3;
    const int bch = (tid & 7) * 8;
    const size_t bstart = (size_t)e * Kdim * Ndim + (size_t)br * Ndim + n0 + bch;
    const __half* pB0h = B0h_g + bstart;
    const __half* pB1h = FUSED ? (B1h_g + bstart) : nullptr;
    const uint32_t dB = (uint32_t)((br * SB + bch) * 2);

    auto issue = [&](int kt, int buf) {
        const uint32_t st = sbase + (uint32_t)buf * STAGE_B;
        const size_t ak = (size_t)kt * 32;
        const size_t bk = (size_t)kt * 32 * Ndim;
        CP16(st + dA,                pAh + ak,     aSz);
        CP16(st + dA + 16,           pAh + ak + 8, aSz);
        CP16(st + dB + B0H * 2,      pB0h + bk,    16u);
        if (FUSED) CP16(st + dB + B1H * 2, pB1h + bk, 16u);
    };

    float accG[4][2][4];
    float accU[FUSED ? 4 : 1][2][4];
    #pragma unroll
    for (int i = 0; i < 4; i++)
        #pragma unroll
        for (int j = 0; j < 2; j++)
            #pragma unroll
            for (int p = 0; p < 4; p++) { accG[i][j][p] = 0.f; if (FUSED) accU[i][j][p] = 0.f; }

    // prologue: issue tiles 0..3 (4 groups), wait until tile 0 resident
    issue(0, 0); CP_COMMIT();
    issue(1, 1); CP_COMMIT();
    issue(2, 2); CP_COMMIT();
    issue(3, 3); CP_COMMIT();
    CP_WAIT3();
    __syncthreads();

    int buf = 0, pbuf = 4;   // compute buffer, prefetch buffer (kt+4)%5
    for (int kt = 0; kt < KT; kt++) {
        if (kt + 4 < KT) issue(kt + 4, pbuf);
        CP_COMMIT();

        const uint32_t st = sbase + (uint32_t)buf * STAGE_B;
        #pragma unroll
        for (int ks = 0; ks < 2; ks++) {
            const uint32_t bks = (uint32_t)(ks * 16 * SB * 2);
            uint32_t bGh[2][2];
            uint32_t bUh[FUSED ? 2 : 1][2];
            {
                uint32_t t0, t1, t2, t3;
                LDSM4T(t0, t1, t2, t3, st + (uint32_t)(B0H * 2) + b_loff + bks);
                bGh[0][0]=t0; bGh[0][1]=t1; bGh[1][0]=t2; bGh[1][1]=t3;
                if (FUSED) {
                    LDSM4T(t0, t1, t2, t3, st + (uint32_t)(B1H * 2) + b_loff + bks);
                    bUh[0][0]=t0; bUh[0][1]=t1; bUh[1][0]=t2; bUh[1][1]=t3;
                }
            }
            #pragma unroll
            for (int mf = 0; mf < 4; mf++) {
                uint32_t ah[4];
                const uint32_t aa = st + a_loff + (uint32_t)(mf * 16 * SA * 2) + (uint32_t)(ks * 32);
                LDSM4(ah[0], ah[1], ah[2], ah[3], aa);
                #pragma unroll
                for (int nf = 0; nf < 2; nf++) {
                    mma16(accG[mf][nf], ah, bGh[nf]);
                    if (FUSED) mma16(accU[mf][nf], ah, bUh[nf]);
                }
            }
        }
        CP_WAIT3();
        __syncthreads();
        buf  = (buf  == 4) ? 0 : buf + 1;
        pbuf = (pbuf == 4) ? 0 : pbuf + 1;
    }

    // ---- epilogue ----
    #pragma unroll
    for (int mf = 0; mf < 4; mf++) {
        #pragma unroll
        for (int h = 0; h < 2; h++) {
            int r = m0 + wm * 64 + mf * 16 + lg + h * 8;
            if (r >= ne) continue;
            int col = n0 + wn * 16 + lt * 2;
            if (FUSED) {
                size_t base = (size_t)(off + r) * INTER + col;
                #pragma unroll
                for (int nf = 0; nf < 2; nf++) {
                    float g0 = accG[mf][nf][2*h],   g1 = accG[mf][nf][2*h+1];
                    float u0 = accU[mf][nf][2*h],   u1 = accU[mf][nf][2*h+1];
                    float h0 = g0 * sigmoidf_fast(g0) * u0;
                    float h1 = g1 * sigmoidf_fast(g1) * u1;
                    *(uint32_t*)(g_hh + base + nf * 8) = cvt2h(h0, h1);
                }
            } else {
                // fused combine: out[token] += w * v (exactly 2 adds/element, commutative)
                int   t = g_tok[e * TOKENS + r];
                float w = g_wslot[e * TOKENS + r];
                float* orow = outp + (size_t)t * HIDDEN + col;
                #pragma unroll
                for (int nf = 0; nf < 2; nf++) {
                    atomicAdd(orow + nf * 8,     w * accG[mf][nf][2*h]);
                    atomicAdd(orow + nf * 8 + 1, w * accG[mf][nf][2*h+1]);
                }
            }
        }
    }
}

// ---------------- launcher ----------------
extern "C" void kernel_launch(void* const* d_in, const int* in_sizes, int n_in,
                              void* d_out, int out_size) {
    const float* X   = (const float*)d_in[0];
    const float* Wg  = (const float*)d_in[1];
    const float* Wgp = (const float*)d_in[2];
    const float* Wup = (const float*)d_in[3];
    const float* Wdp = (const float*)d_in[4];
    float* out = (float*)d_out;

    __half *xh, *w0h, *w1h, *wdh, *hh;
    cudaGetSymbolAddress((void**)&xh,  c_Xh);
    cudaGetSymbolAddress((void**)&w0h, c_W0h);
    cudaGetSymbolAddress((void**)&w1h, c_W1h);
    cudaGetSymbolAddress((void**)&wdh, c_Wdh);
    cudaGetSymbolAddress((void**)&hh,  g_hh);

    constexpr int STAGE_F = (128*40 + 2*32*72) * 2;   // 19456 B
    constexpr int STAGE_D = (128*40 + 1*32*72) * 2;   // 14848 B
    const int SMEM_F = 5 * STAGE_F;                   // 97280
    const int SMEM_D = 5 * STAGE_D;                   // 74240
    cudaFuncSetAttribute(moe_gemm_fp16<1>, cudaFuncAttributeMaxDynamicSharedMemorySize, SMEM_F);
    cudaFuncSetAttribute(moe_gemm_fp16<0>, cudaFuncAttributeMaxDynamicSharedMemorySize, SMEM_D);

    // ONE aux stream + 4 events (proven-safe footprint)
    static cudaStream_t sAux = nullptr;
    static cudaEvent_t  evFork = nullptr, evX = nullptr, evWm = nullptr, evWd = nullptr;
    if (sAux == nullptr) {
        cudaStreamCreateWithFlags(&sAux, cudaStreamNonBlocking);
        cudaEventCreateWithFlags(&evFork, cudaEventDisableTiming);
        cudaEventCreateWithFlags(&evX,    cudaEventDisableTiming);
        cudaEventCreateWithFlags(&evWm,   cudaEventDisableTiming);
        cudaEventCreateWithFlags(&evWd,   cudaEventDisableTiming);
    }

    const int NX = TOKENS * HIDDEN / 8;
    const int NW = EXPERTS * HIDDEN * INTER / 8;

    // ---- fork aux off the main (capture) stream ----
    cudaEventRecord(evFork, 0);
    cudaStreamWaitEvent(sAux, evFork, 0);

    // aux: routing + X conversion (light); Wd cvt deferred under the fused GEMM
    zero_cnt_kernel<<<1, 32, 0, sAux>>>();
    router_logits_kernel<<<(TOKENS * EXPERTS) / 256, 256, 0, sAux>>>(X, Wg);
    router_topk_kernel<<<(TOKENS + 255) / 256, 256, 0, sAux>>>();
    offsets_kernel<<<1, 1, 0, sAux>>>();
    cvt_kernel<<<(NX + 255) / 256, 256, 0, sAux>>>(X, xh, NX);
    cudaEventRecord(evX, sAux);

    // main: zero output (needed before down GEMM's atomics), then W0/W1 cvt
    zero_out_kernel<<<(TOKENS * HIDDEN / 4) / 256, 256>>>(out);
    cvt_kernel<<<(NW + 255) / 256, 256>>>(Wgp, w0h, NW);
    cvt_kernel<<<(NW + 255) / 256, 256>>>(Wup, w1h, NW);
    cudaEventRecord(evWm, 0);

    // aux: Wd conversion overlapped with fused GEMM
    cudaStreamWaitEvent(sAux, evWm, 0);
    cvt_kernel<<<(NW + 255) / 256, 256, 0, sAux>>>(Wdp, wdh, NW);
    cudaEventRecord(evWd, sAux);

    // main: fused GEMM (needs router + xh via evX; w0h/w1h via stream order)
    cudaStreamWaitEvent(0, evX, 0);
    dim3 grid_f(TOKENS / 128, INTER / 64, EXPERTS);    // (16, 22, 16)
    moe_gemm_fp16<1><<<grid_f, 256, SMEM_F>>>(xh, w0h, w1h, nullptr, 0);

    // main: down GEMM with fused combine (needs g_hh + zeroed out via stream order, wdh via event)
    cudaStreamWaitEvent(0, evWd, 0);
    dim3 grid_d(TOKENS / 128, HIDDEN / 64, EXPERTS);   // (16, 32, 16)
    moe_gemm_fp16<0><<<grid_d, 256, SMEM_D>>>(hh, wdh, nullptr, out, 0);
}